// round 11
// baseline (speedup 1.0000x reference)
#include <cuda_runtime.h>
#include <cuda_fp16.h>
#include <cstdint>

// GPT2 attention block, fp16 mma.sync (m16n8k16, fp32 accum) + cp.async.
// B=2, S=2048, D=768, H=12, hd=64

#define B_ 2
#define S_ 2048
#define D_ 768
#define H_ 12
#define HD_ 64
#define M_ (B_ * S_)        // 4096
#define N_QKV (3 * D_)      // 2304
#define MASKED_BIAS (-10000.0f)
#define L2E 1.4426950408889634f

// Scratch (no cudaMalloc allowed) — all fp16
__device__ __align__(128) __half g_q[B_ * H_ * S_ * HD_];   // [b,h,s,d], pre-scaled 1/8
__device__ __align__(128) __half g_k[B_ * H_ * S_ * HD_];   // [b,h,s,d]
__device__ __align__(128) __half g_v[B_ * H_ * S_ * HD_];   // [b,h,d,s]  (TRANSPOSED)
__device__ __align__(128) __half g_att[M_ * D_];
__device__ __align__(128) __half g_x[M_ * D_];              // hidden fp16
__device__ __align__(128) __half g_wqkv_t[N_QKV * D_];      // [n][k]
__device__ __align__(128) __half g_wp_t[D_ * D_];           // [n][k]

// ---------------------------------------------------------------------------
__device__ __forceinline__ uint32_t packh2(float lo, float hi) {
    __half2 h = __floats2half2_rn(lo, hi);
    return *(uint32_t*)&h;
}
__device__ __forceinline__ uint32_t ex2h2(uint32_t x) {
    uint32_t y;
    asm("ex2.approx.f16x2 %0, %1;" : "=r"(y) : "r"(x));
    return y;
}
__device__ __forceinline__ void mma_f16(float d[4], const uint32_t a[4],
                                        const uint32_t b0, const uint32_t b1,
                                        const float c[4]) {
    asm volatile(
        "mma.sync.aligned.m16n8k16.row.col.f32.f16.f16.f32 "
        "{%0,%1,%2,%3}, {%4,%5,%6,%7}, {%8,%9}, {%10,%11,%12,%13};\n"
        : "=f"(d[0]), "=f"(d[1]), "=f"(d[2]), "=f"(d[3])
        : "r"(a[0]), "r"(a[1]), "r"(a[2]), "r"(a[3]),
          "r"(b0), "r"(b1),
          "f"(c[0]), "f"(c[1]), "f"(c[2]), "f"(c[3]));
}
__device__ __forceinline__ void ldsm4(uint32_t r[4], uint32_t addr) {
    asm volatile("ldmatrix.sync.aligned.m8n8.x4.shared.b16 {%0,%1,%2,%3}, [%4];"
        : "=r"(r[0]), "=r"(r[1]), "=r"(r[2]), "=r"(r[3]) : "r"(addr));
}
__device__ __forceinline__ void cp16(uint32_t dst, const void* src) {
    asm volatile("cp.async.cg.shared.global [%0], [%1], 16;\n"
                 :: "r"(dst), "l"(src));
}
__device__ __forceinline__ void cp_commit() {
    asm volatile("cp.async.commit_group;\n");
}
template <int N>
__device__ __forceinline__ void cp_wait() {
    asm volatile("cp.async.wait_group %0;\n" :: "n"(N));
}

// ---------------------------------------------------------------------------
// Fused pre-pass: one launch does hidden cvt + both weight transposes.
// ---------------------------------------------------------------------------
#define NB_CVT (M_ * D_ / 4 / 256)          // 3072
#define NB_TQ  ((N_QKV / 32) * (D_ / 32))   // 1728
#define NB_TP  ((D_ / 32) * (D_ / 32))      // 576

__global__ __launch_bounds__(256) void prepass(
    const float* __restrict__ hidden,
    const float* __restrict__ wq,
    const float* __restrict__ wp)
{
    const int bid = blockIdx.x;
    const int tid = threadIdx.x;

    if (bid < NB_CVT) {
        int i = bid * 256 + tid;
        float4 v = ((const float4*)hidden)[i];
        uint2 t;
        t.x = packh2(v.x, v.y);
        t.y = packh2(v.z, v.w);
        ((uint2*)g_x)[i] = t;
        return;
    }

    const float* src;
    __half* dst;
    int R, C, bx, by;
    if (bid < NB_CVT + NB_TQ) {
        int bi = bid - NB_CVT;
        src = wq; dst = g_wqkv_t; R = D_; C = N_QKV;
        bx = bi % (N_QKV / 32); by = bi / (N_QKV / 32);
    } else {
        int bi = bid - NB_CVT - NB_TQ;
        src = wp; dst = g_wp_t; R = D_; C = D_;
        bx = bi % (D_ / 32); by = bi / (D_ / 32);
    }

    __shared__ float tile[32][33];
    const int c0 = bx * 32, r0 = by * 32;
    const int x = tid & 31, y = tid >> 5;
#pragma unroll
    for (int j = 0; j < 32; j += 8)
        tile[y + j][x] = src[(size_t)(r0 + y + j) * C + c0 + x];
    __syncthreads();
#pragma unroll
    for (int j = 0; j < 32; j += 8)
        dst[(size_t)(c0 + y + j) * R + r0 + x] = __float2half(tile[x][y + j]);
}

// ---------------------------------------------------------------------------
// FP16 GEMM: 128 x BN_ x 64 tile, THREADS threads, cp.async 3-stage,
// XOR-swizzled smem, ldmatrix.
//   GEMM1: MODE 0, BN=128, 256 thr, occ 2 — 8 warps of 64x32 (MT=4).
//   proj : MODE 1, BN= 64, 128 thr, occ 3 — 4 warps of 64x32 (MT=4).
// ---------------------------------------------------------------------------
template <int MODE, int BN_, int THREADS, int OCC>
__global__ __launch_bounds__(THREADS, OCC) void mma_gemm(
    const __half* __restrict__ A,   // [M][K]
    const __half* __restrict__ Bt,  // [N][K]
    const float* __restrict__ bias,
    float* __restrict__ Cout,
    int K, int N)
{
    constexpr int BM = 128, BN = BN_, BK = 64;            // BK in halfs (128B)
    constexpr int STAGE_BYTES = (BM + BN) * 128;
    constexpr int NWARPS = THREADS / 32;
    constexpr int WN_CNT = BN / 32;
    constexpr int WM_CNT = NWARPS / WN_CNT;
    constexpr int MT = 128 / (WM_CNT * 16);
    constexpr int ROWS_PASS = THREADS / 8;                // rows per loader pass
    constexpr int APASS = BM / ROWS_PASS;
    constexpr int BPASS = BN / ROWS_PASS;

    extern __shared__ uint32_t smem[];
    const uint32_t sbase = (uint32_t)__cvta_generic_to_shared(smem);

    const int tid = threadIdx.x;
    const int lane = tid & 31;
    const int wid = tid >> 5;
    const int wm = wid % WM_CNT, wn = wid / WM_CNT;
    const int gid = lane >> 2, tig = lane & 3, l7 = lane & 7;
    const int bm = blockIdx.y, bn = blockIdx.x;

    // loader: ROWS_PASS rows x 8 groups per pass
    const int row_ = tid >> 3, g_ = tid & 7;
    const __half* asrc = A + (size_t)(bm * BM + row_) * K + g_ * 8;
    const __half* bsrc = Bt + (size_t)(bn * BN + row_) * K + g_ * 8;
    const uint32_t dofs = (uint32_t)(row_ * 128 + ((g_ ^ (row_ & 7)) * 16));

    auto issue = [&](int s, int kt) {
        const uint32_t sb = sbase + (uint32_t)(s * STAGE_BYTES);
        const __half* ap = asrc + kt * BK;
        const __half* bp = bsrc + kt * BK;
        const uint32_t ad = sb + dofs;
        const uint32_t bd = ad + (uint32_t)(BM * 128);
#pragma unroll
        for (int u = 0; u < APASS; u++)
            cp16(ad + u * (ROWS_PASS * 128), ap + (size_t)u * ROWS_PASS * K);
#pragma unroll
        for (int u = 0; u < BPASS; u++)
            cp16(bd + u * (ROWS_PASS * 128), bp + (size_t)u * ROWS_PASS * K);
    };

    // fragment addressing (bytes)
    const uint32_t arowb =
        (uint32_t)((wm * (MT * 16) + l7 + ((lane >> 3) & 1) * 8) * 128);
    const uint32_t browb =
        (uint32_t)((wn * 32 + l7 + ((lane >> 4) & 1) * 8) * 128)
        + (uint32_t)(BM * 128);
    uint32_t aswz[4], bswz[4];
#pragma unroll
    for (int kk = 0; kk < 4; kk++) {
        aswz[kk] = (uint32_t)((((kk * 2 + (lane >> 4)) ^ l7)) * 16);
        bswz[kk] = (uint32_t)((((kk * 2 + ((lane >> 3) & 1)) ^ l7)) * 16);
    }

    float acc[MT][4][4];
#pragma unroll
    for (int i = 0; i < MT; i++)
#pragma unroll
        for (int j = 0; j < 4; j++)
#pragma unroll
            for (int r = 0; r < 4; r++) acc[i][j][r] = 0.f;

    issue(0, 0); cp_commit();
    issue(1, 1); cp_commit();

    const int ksteps = K / BK;   // 12
    int st = 0;
    for (int kt = 0; kt < ksteps; kt++) {
        cp_wait<1>();
        __syncthreads();
        if (kt + 2 < ksteps) {
            int s2 = st + 2; if (s2 >= 3) s2 -= 3;
            issue(s2, kt + 2);
        }
        cp_commit();

        const uint32_t sb = sbase + (uint32_t)(st * STAGE_BYTES);
#pragma unroll
        for (int kk = 0; kk < 4; kk++) {
            uint32_t bf[2][4];
#pragma unroll
            for (int ntp = 0; ntp < 2; ntp++)
                ldsm4(bf[ntp], sb + browb + ntp * (16 * 128) + bswz[kk]);
            uint32_t af[MT][4];
#pragma unroll
            for (int mt = 0; mt < MT; mt++)
                ldsm4(af[mt], sb + arowb + mt * (16 * 128) + aswz[kk]);
#pragma unroll
            for (int mt = 0; mt < MT; mt++)
#pragma unroll
                for (int ntp = 0; ntp < 2; ntp++) {
                    mma_f16(acc[mt][ntp * 2],     af[mt], bf[ntp][0], bf[ntp][1],
                            acc[mt][ntp * 2]);
                    mma_f16(acc[mt][ntp * 2 + 1], af[mt], bf[ntp][2], bf[ntp][3],
                            acc[mt][ntp * 2 + 1]);
                }
        }
        if (++st == 3) st = 0;
    }

    // epilogue
#pragma unroll
    for (int mt = 0; mt < MT; mt++) {
#pragma unroll
        for (int nt = 0; nt < 4; nt++) {
#pragma unroll
            for (int r = 0; r < 4; r++) {
                int m = bm * BM + wm * (MT * 16) + mt * 16 + gid + ((r >= 2) ? 8 : 0);
                int n = bn * BN + wn * 32 + nt * 8 + 2 * tig + (r & 1);
                float val = acc[mt][nt][r] + bias[n];
                if (MODE == 0) {
                    const int which = n / D_;
                    const int d2 = n - which * D_;
                    const int h = d2 >> 6;
                    const int hi = d2 & 63;
                    const int b = m >> 11;
                    const int s = m & 2047;
                    if (which == 0) {
                        g_q[(((size_t)(b * H_ + h) * S_) + s) * HD_ + hi] =
                            __float2half(val * 0.125f);
                    } else if (which == 1) {
                        g_k[(((size_t)(b * H_ + h) * S_) + s) * HD_ + hi] =
                            __float2half(val);
                    } else {
                        g_v[((size_t)(b * H_ + h) * HD_ + hi) * S_ + s] =
                            __float2half(val);
                    }
                } else {
                    Cout[(size_t)m * N + n] = val;
                }
            }
        }
    }
}

// ---------------------------------------------------------------------------
// Flash attention, fp16 mma m16n8k16. 128 threads (4 warps), Br=64, Bc=64.
// 4-stage cp.async ring, prefetch distance 2, single __syncthreads per tile.
// exp via ex2.approx.f16x2 — P lands directly in the PV A-fragment.
// ---------------------------------------------------------------------------
__global__ __launch_bounds__(128, 3) void attn_mma()
{
    const int qtile = gridDim.x - 1 - blockIdx.x;   // heavy tiles first
    const int h = blockIdx.y;
    const int b = blockIdx.z;
    const int tid = threadIdx.x;
    const int lane = tid & 31;
    const int wid = tid >> 5;
    const int gid = lane >> 2, tig = lane & 3, l7 = lane & 7;

    const int q0 = qtile * 64;
    const int wrow0 = q0 + wid * 16;

    const uint32_t* qu = (const uint32_t*)(g_q + ((size_t)(b * H_ + h) * S_) * HD_);
    const __half* kb = g_k + ((size_t)(b * H_ + h) * S_) * HD_;
    const __half* vtb = g_v + ((size_t)(b * H_ + h) * HD_) * S_;

    uint32_t qf[4][4];
#pragma unroll
    for (int kk = 0; kk < 4; kk++) {
        const int r0 = wrow0 + gid;
        const int u0 = r0 * 32 + kk * 8 + tig;
        const int u1 = (r0 + 8) * 32 + kk * 8 + tig;
        qf[kk][0] = qu[u0];
        qf[kk][1] = qu[u1];
        qf[kk][2] = qu[u0 + 4];
        qf[kk][3] = qu[u1 + 4];
    }

    float o[8][4];
#pragma unroll
    for (int nt = 0; nt < 8; nt++)
#pragma unroll
        for (int r = 0; r < 4; r++) o[nt][r] = 0.f;
    float m0 = -1e30f, m1 = -1e30f, l0 = 0.f, l1 = 0.f;

    extern __shared__ uint32_t asmem[];   // [4][16KB]: K 8KB + Vt 8KB per stage
    const uint32_t sbase = (uint32_t)__cvta_generic_to_shared(asmem);

    const int row_ = tid >> 3, g_ = tid & 7;
    const uint32_t dofs = (uint32_t)(row_ * 128 + ((g_ ^ (row_ & 7)) * 16));

    auto issueT = [&](int s, int t) {
        const int k0 = t * 64;
        const uint32_t kd = sbase + (uint32_t)(s * 16384) + dofs;
        const uint32_t vd = kd + 8192;
        const __half* kp = kb + (size_t)(k0 + row_) * HD_ + g_ * 8;
        const __half* vp = vtb + (size_t)row_ * S_ + k0 + g_ * 8;
#pragma unroll
        for (int u = 0; u < 4; u++) {
            cp16(kd + u * (16 * 128), kp + (size_t)u * 16 * HD_);
            cp16(vd + u * (16 * 128), vp + (size_t)u * 16 * S_);
        }
    };

    const uint32_t rowbB = (uint32_t)((l7 + ((lane >> 4) & 1) * 8) * 128);
    uint32_t bswz[4];
#pragma unroll
    for (int kk = 0; kk < 4; kk++)
        bswz[kk] = (uint32_t)((((kk * 2 + ((lane >> 3) & 1)) ^ l7)) * 16);

    issueT(0, 0); cp_commit();
    if (qtile >= 1) issueT(1, 1);
    cp_commit();

    for (int t = 0; t <= qtile; t++) {
        cp_wait<1>();
        __syncthreads();
        if (t + 2 <= qtile) issueT((t + 2) & 3, t + 2);
        cp_commit();

        const uint32_t baseK = sbase + (uint32_t)((t & 3) * 16384);
        const uint32_t baseV = baseK + 8192;
        const int k0 = t * 64;

        float sfr[8][4];
#pragma unroll
        for (int nt = 0; nt < 8; nt++)
#pragma unroll
            for (int r = 0; r < 4; r++) sfr[nt][r] = 0.f;
#pragma unroll
        for (int kk = 0; kk < 4; kk++) {
#pragma unroll
            for (int ntp = 0; ntp < 4; ntp++) {
                uint32_t bf[4];
                ldsm4(bf, baseK + ntp * (16 * 128) + rowbB + bswz[kk]);
                mma_f16(sfr[ntp * 2],     qf[kk], bf[0], bf[1], sfr[ntp * 2]);
                mma_f16(sfr[ntp * 2 + 1], qf[kk], bf[2], bf[3], sfr[ntp * 2 + 1]);
            }
        }

        const int r0 = wrow0 + gid;
        const int r1 = r0 + 8;
        if (k0 + 63 > wrow0) {
#pragma unroll
            for (int nt = 0; nt < 8; nt++) {
                int c = k0 + nt * 8 + 2 * tig;
                if (c > r0) sfr[nt][0] = MASKED_BIAS;
                if (c + 1 > r0) sfr[nt][1] = MASKED_BIAS;
                if (c > r1) sfr[nt][2] = MASKED_BIAS;
                if (c + 1 > r1) sfr[nt][3] = MASKED_BIAS;
            }
        }

        float mx0 = -1e30f, mx1 = -1e30f;
#pragma unroll
        for (int nt = 0; nt < 8; nt++) {
            mx0 = fmaxf(mx0, fmaxf(sfr[nt][0], sfr[nt][1]));
            mx1 = fmaxf(mx1, fmaxf(sfr[nt][2], sfr[nt][3]));
        }
        mx0 = fmaxf(mx0, __shfl_xor_sync(0xffffffffu, mx0, 1));
        mx0 = fmaxf(mx0, __shfl_xor_sync(0xffffffffu, mx0, 2));
        mx1 = fmaxf(mx1, __shfl_xor_sync(0xffffffffu, mx1, 1));
        mx1 = fmaxf(mx1, __shfl_xor_sync(0xffffffffu, mx1, 2));

        const float mn0 = fmaxf(m0, mx0);
        const float mn1 = fmaxf(m1, mx1);
        float a0, a1;
        {
            uint32_t sc = ex2h2(packh2((m0 - mn0) * L2E, (m1 - mn1) * L2E));
            float2 scf = __half22float2(*(__half2*)&sc);
            a0 = scf.x; a1 = scf.y;
        }
        m0 = mn0; m1 = mn1;
        const float b0l = m0 * L2E;
        const float b1l = m1 * L2E;

        uint32_t pf[4][4];
#pragma unroll
        for (int nt = 0; nt < 8; nt++) {
            uint32_t ha = packh2(fmaf(sfr[nt][0], L2E, -b0l),
                                 fmaf(sfr[nt][1], L2E, -b0l));
            uint32_t hb = packh2(fmaf(sfr[nt][2], L2E, -b1l),
                                 fmaf(sfr[nt][3], L2E, -b1l));
            pf[nt >> 1][(nt & 1) * 2]     = ex2h2(ha);
            pf[nt >> 1][(nt & 1) * 2 + 1] = ex2h2(hb);
        }

        float ls0 = 0.f, ls1 = 0.f;
#pragma unroll
        for (int kv = 0; kv < 4; kv++) {
            __half2 s0 = __hadd2(*(__half2*)&pf[kv][0], *(__half2*)&pf[kv][2]);
            __half2 s1 = __hadd2(*(__half2*)&pf[kv][1], *(__half2*)&pf[kv][3]);
            float2 f0 = __half22float2(s0);
            float2 f1 = __half22float2(s1);
            ls0 += f0.x + f0.y;
            ls1 += f1.x + f1.y;
        }
        ls0 += __shfl_xor_sync(0xffffffffu, ls0, 1);
        ls0 += __shfl_xor_sync(0xffffffffu, ls0, 2);
        ls1 += __shfl_xor_sync(0xffffffffu, ls1, 1);
        ls1 += __shfl_xor_sync(0xffffffffu, ls1, 2);
        l0 = l0 * a0 + ls0;
        l1 = l1 * a1 + ls1;

#pragma unroll
        for (int nt = 0; nt < 8; nt++) {
            o[nt][0] *= a0; o[nt][1] *= a0;
            o[nt][2] *= a1; o[nt][3] *= a1;
        }

#pragma unroll
        for (int kkv = 0; kkv < 4; kkv++) {
#pragma unroll
            for (int ntp = 0; ntp < 4; ntp++) {
                uint32_t bf[4];
                ldsm4(bf, baseV + ntp * (16 * 128) + rowbB + bswz[kkv]);
                mma_f16(o[ntp * 2],     pf[kkv], bf[0], bf[1], o[ntp * 2]);
                mma_f16(o[ntp * 2 + 1], pf[kkv], bf[2], bf[3], o[ntp * 2 + 1]);
            }
        }
    }

    const float inv0 = 1.f / l0;
    const float inv1 = 1.f / l1;
    const int r0 = wrow0 + gid;
    uint32_t* ob0 = (uint32_t*)(g_att + ((size_t)(b * S_ + r0)) * D_ + h * HD_);
    uint32_t* ob1 = (uint32_t*)(g_att + ((size_t)(b * S_ + r0 + 8)) * D_ + h * HD_);
#pragma unroll
    for (int nt = 0; nt < 8; nt++) {
        ob0[nt * 4 + tig] = packh2(o[nt][0] * inv0, o[nt][1] * inv0);
        ob1[nt * 4 + tig] = packh2(o[nt][2] * inv1, o[nt][3] * inv1);
    }
}

// ---------------------------------------------------------------------------
extern "C" void kernel_launch(void* const* d_in, const int* in_sizes, int n_in,
                              void* d_out, int out_size)
{
    const float* hidden   = (const float*)d_in[0];
    const float* c_attn_w = (const float*)d_in[1];
    const float* c_attn_b = (const float*)d_in[2];
    const float* c_proj_w = (const float*)d_in[3];
    const float* c_proj_b = (const float*)d_in[4];
    float* out = (float*)d_out;

    constexpr int SMEM_G128 = 3 * (128 + 128) * 128;   // 96KB
    constexpr int SMEM_G64  = 3 * (128 + 64) * 128;    // 72KB
    constexpr int SMEM_ATTN = 4 * 16384;               // 64KB

    static bool attr_set = false;
    if (!attr_set) {
        cudaFuncSetAttribute((const void*)mma_gemm<0, 128, 256, 2>,
            cudaFuncAttributeMaxDynamicSharedMemorySize, SMEM_G128);
        cudaFuncSetAttribute((const void*)mma_gemm<1, 64, 128, 3>,
            cudaFuncAttributeMaxDynamicSharedMemorySize, SMEM_G64);
        cudaFuncSetAttribute((const void*)attn_mma,
            cudaFuncAttributeMaxDynamicSharedMemorySize, SMEM_ATTN);
        attr_set = true;
    }

    __half *px, *pwq, *pwp, *patt;
    cudaGetSymbolAddress((void**)&px, g_x);
    cudaGetSymbolAddress((void**)&pwq, g_wqkv_t);
    cudaGetSymbolAddress((void**)&pwp, g_wp_t);
    cudaGetSymbolAddress((void**)&patt, g_att);

    // Fused pre-pass (1 launch)
    prepass<<<NB_CVT + NB_TQ + NB_TP, 256>>>(hidden, c_attn_w, c_proj_w);

    // Phase 1: QKV GEMM + head split (+ q scaling, v transpose)
    {
        dim3 grid(N_QKV / 128, M_ / 128);   // (18, 32) = 576, occ2 -> 2 waves
        mma_gemm<0, 128, 256, 2><<<grid, 256, SMEM_G128>>>(
            px, pwq, c_attn_b, nullptr, D_, N_QKV);
    }
    // Phase 2: causal flash attention, Br=64
    {
        dim3 grid(S_ / 64, H_, B_);         // (32, 12, 2)
        attn_mma<<<grid, 128, SMEM_ATTN>>>();
    }
    // Phase 3: output projection — 128-thr CTAs, occ 3 -> 384 blocks, 1 wave
    {
        dim3 grid(D_ / 64, M_ / 128);       // (12, 32) = 384
        mma_gemm<1, 64, 128, 3><<<grid, 128, SMEM_G64>>>(
            patt, pwp, c_proj_b, out, D_, D_);
    }
}

// round 12
// speedup vs baseline: 1.0892x; 1.0892x over previous
#include <cuda_runtime.h>
#include <cuda_fp16.h>
#include <cstdint>

// GPT2 attention block, fp16 mma.sync (m16n8k16, fp32 accum) + cp.async.
// B=2, S=2048, D=768, H=12, hd=64

#define B_ 2
#define S_ 2048
#define D_ 768
#define H_ 12
#define HD_ 64
#define M_ (B_ * S_)        // 4096
#define N_QKV (3 * D_)      // 2304
#define MASKED_BIAS (-10000.0f)
#define L2E 1.4426950408889634f

// Scratch (no cudaMalloc allowed) — all fp16
__device__ __align__(128) __half g_q[B_ * H_ * S_ * HD_];   // [b,h,s,d], pre-scaled 1/8
__device__ __align__(128) __half g_k[B_ * H_ * S_ * HD_];   // [b,h,s,d]
__device__ __align__(128) __half g_v[B_ * H_ * S_ * HD_];   // [b,h,d,s]  (TRANSPOSED)
__device__ __align__(128) __half g_att[M_ * D_];
__device__ __align__(128) __half g_x[M_ * D_];              // hidden fp16
__device__ __align__(128) __half g_wqkv_t[N_QKV * D_];      // [n][k]
__device__ __align__(128) __half g_wp_t[D_ * D_];           // [n][k]

// ---------------------------------------------------------------------------
__device__ __forceinline__ uint32_t packh2(float lo, float hi) {
    __half2 h = __floats2half2_rn(lo, hi);
    return *(uint32_t*)&h;
}
__device__ __forceinline__ uint32_t ex2h2(uint32_t x) {
    uint32_t y;
    asm("ex2.approx.f16x2 %0, %1;" : "=r"(y) : "r"(x));
    return y;
}
__device__ __forceinline__ void mma_f16(float d[4], const uint32_t a[4],
                                        const uint32_t b0, const uint32_t b1,
                                        const float c[4]) {
    asm volatile(
        "mma.sync.aligned.m16n8k16.row.col.f32.f16.f16.f32 "
        "{%0,%1,%2,%3}, {%4,%5,%6,%7}, {%8,%9}, {%10,%11,%12,%13};\n"
        : "=f"(d[0]), "=f"(d[1]), "=f"(d[2]), "=f"(d[3])
        : "r"(a[0]), "r"(a[1]), "r"(a[2]), "r"(a[3]),
          "r"(b0), "r"(b1),
          "f"(c[0]), "f"(c[1]), "f"(c[2]), "f"(c[3]));
}
__device__ __forceinline__ void ldsm4(uint32_t r[4], uint32_t addr) {
    asm volatile("ldmatrix.sync.aligned.m8n8.x4.shared.b16 {%0,%1,%2,%3}, [%4];"
        : "=r"(r[0]), "=r"(r[1]), "=r"(r[2]), "=r"(r[3]) : "r"(addr));
}
__device__ __forceinline__ void cp16(uint32_t dst, const void* src) {
    asm volatile("cp.async.cg.shared.global [%0], [%1], 16;\n"
                 :: "r"(dst), "l"(src));
}
__device__ __forceinline__ void cp_commit() {
    asm volatile("cp.async.commit_group;\n");
}
template <int N>
__device__ __forceinline__ void cp_wait() {
    asm volatile("cp.async.wait_group %0;\n" :: "n"(N));
}

// ---------------------------------------------------------------------------
// Fused pre-pass: one launch does hidden cvt + both weight transposes.
// ---------------------------------------------------------------------------
#define NB_CVT (M_ * D_ / 4 / 256)          // 3072
#define NB_TQ  ((N_QKV / 32) * (D_ / 32))   // 1728
#define NB_TP  ((D_ / 32) * (D_ / 32))      // 576

__global__ __launch_bounds__(256) void prepass(
    const float* __restrict__ hidden,
    const float* __restrict__ wq,
    const float* __restrict__ wp)
{
    const int bid = blockIdx.x;
    const int tid = threadIdx.x;

    if (bid < NB_CVT) {
        int i = bid * 256 + tid;
        float4 v = ((const float4*)hidden)[i];
        uint2 t;
        t.x = packh2(v.x, v.y);
        t.y = packh2(v.z, v.w);
        ((uint2*)g_x)[i] = t;
        return;
    }

    const float* src;
    __half* dst;
    int R, C, bx, by;
    if (bid < NB_CVT + NB_TQ) {
        int bi = bid - NB_CVT;
        src = wq; dst = g_wqkv_t; R = D_; C = N_QKV;
        bx = bi % (N_QKV / 32); by = bi / (N_QKV / 32);
    } else {
        int bi = bid - NB_CVT - NB_TQ;
        src = wp; dst = g_wp_t; R = D_; C = D_;
        bx = bi % (D_ / 32); by = bi / (D_ / 32);
    }

    __shared__ float tile[32][33];
    const int c0 = bx * 32, r0 = by * 32;
    const int x = tid & 31, y = tid >> 5;
#pragma unroll
    for (int j = 0; j < 32; j += 8)
        tile[y + j][x] = src[(size_t)(r0 + y + j) * C + c0 + x];
    __syncthreads();
#pragma unroll
    for (int j = 0; j < 32; j += 8)
        dst[(size_t)(c0 + y + j) * R + r0 + x] = __float2half(tile[x][y + j]);
}

// ---------------------------------------------------------------------------
// FP16 GEMM: 128 x BN_ x 64 tile, 256 threads (8 warps), cp.async 3-stage,
// XOR-swizzled smem, ldmatrix. BN_ in {128, 64}.
// MODE 0: scatter into g_q (scaled), g_k, g_v(transposed).  MODE 1: Cout f32.
// ---------------------------------------------------------------------------
template <int MODE, int BN_>
__global__ __launch_bounds__(256, 2) void mma_gemm(
    const __half* __restrict__ A,   // [M][K]
    const __half* __restrict__ Bt,  // [N][K]
    const float* __restrict__ bias,
    float* __restrict__ Cout,
    int K, int N)
{
    constexpr int BM = 128, BN = BN_, BK = 64;            // BK in halfs (128B)
    constexpr int STAGE_BYTES = (BM + BN) * 128;
    constexpr int WN_CNT = BN / 32;                       // 4 or 2
    constexpr int WM_CNT = 8 / WN_CNT;                    // 2 or 4
    constexpr int MT = 128 / (WM_CNT * 16);               // 4 or 2
    constexpr int BPASS = BN / 32;                        // B loader passes

    extern __shared__ uint32_t smem[];
    const uint32_t sbase = (uint32_t)__cvta_generic_to_shared(smem);

    const int tid = threadIdx.x;
    const int lane = tid & 31;
    const int wid = tid >> 5;
    const int wm = wid % WM_CNT, wn = wid / WM_CNT;
    const int gid = lane >> 2, tig = lane & 3, l7 = lane & 7;
    const int bm = blockIdx.y, bn = blockIdx.x;

    // loader: 32 rows x 8 groups per pass
    const int row_ = tid >> 3, g_ = tid & 7;
    const __half* asrc = A + (size_t)(bm * BM + row_) * K + g_ * 8;
    const __half* bsrc = Bt + (size_t)(bn * BN + row_) * K + g_ * 8;
    const uint32_t dofs = (uint32_t)(row_ * 128 + ((g_ ^ (row_ & 7)) * 16));

    auto issue = [&](int s, int kt) {
        const uint32_t sb = sbase + (uint32_t)(s * STAGE_BYTES);
        const __half* ap = asrc + kt * BK;
        const __half* bp = bsrc + kt * BK;
        const uint32_t ad = sb + dofs;
        const uint32_t bd = ad + (uint32_t)(BM * 128);
#pragma unroll
        for (int u = 0; u < 4; u++)
            cp16(ad + u * (32 * 128), ap + (size_t)u * 32 * K);
#pragma unroll
        for (int u = 0; u < BPASS; u++)
            cp16(bd + u * (32 * 128), bp + (size_t)u * 32 * K);
    };

    // fragment addressing (bytes)
    const uint32_t arowb =
        (uint32_t)((wm * (MT * 16) + l7 + ((lane >> 3) & 1) * 8) * 128);
    const uint32_t browb =
        (uint32_t)((wn * 32 + l7 + ((lane >> 4) & 1) * 8) * 128)
        + (uint32_t)(BM * 128);
    uint32_t aswz[4], bswz[4];
#pragma unroll
    for (int kk = 0; kk < 4; kk++) {
        aswz[kk] = (uint32_t)((((kk * 2 + (lane >> 4)) ^ l7)) * 16);
        bswz[kk] = (uint32_t)((((kk * 2 + ((lane >> 3) & 1)) ^ l7)) * 16);
    }

    float acc[MT][4][4];
#pragma unroll
    for (int i = 0; i < MT; i++)
#pragma unroll
        for (int j = 0; j < 4; j++)
#pragma unroll
            for (int r = 0; r < 4; r++) acc[i][j][r] = 0.f;

    issue(0, 0); cp_commit();
    issue(1, 1); cp_commit();

    const int ksteps = K / BK;   // 12
    int st = 0;
    for (int kt = 0; kt < ksteps; kt++) {
        cp_wait<1>();
        __syncthreads();
        if (kt + 2 < ksteps) {
            int s2 = st + 2; if (s2 >= 3) s2 -= 3;
            issue(s2, kt + 2);
        }
        cp_commit();

        const uint32_t sb = sbase + (uint32_t)(st * STAGE_BYTES);
#pragma unroll
        for (int kk = 0; kk < 4; kk++) {
            uint32_t bf[2][4];
#pragma unroll
            for (int ntp = 0; ntp < 2; ntp++)
                ldsm4(bf[ntp], sb + browb + ntp * (16 * 128) + bswz[kk]);
            uint32_t af[MT][4];
#pragma unroll
            for (int mt = 0; mt < MT; mt++)
                ldsm4(af[mt], sb + arowb + mt * (16 * 128) + aswz[kk]);
#pragma unroll
            for (int mt = 0; mt < MT; mt++)
#pragma unroll
                for (int ntp = 0; ntp < 2; ntp++) {
                    mma_f16(acc[mt][ntp * 2],     af[mt], bf[ntp][0], bf[ntp][1],
                            acc[mt][ntp * 2]);
                    mma_f16(acc[mt][ntp * 2 + 1], af[mt], bf[ntp][2], bf[ntp][3],
                            acc[mt][ntp * 2 + 1]);
                }
        }
        if (++st == 3) st = 0;
    }

    // epilogue
#pragma unroll
    for (int mt = 0; mt < MT; mt++) {
#pragma unroll
        for (int nt = 0; nt < 4; nt++) {
#pragma unroll
            for (int r = 0; r < 4; r++) {
                int m = bm * BM + wm * (MT * 16) + mt * 16 + gid + ((r >= 2) ? 8 : 0);
                int n = bn * BN + wn * 32 + nt * 8 + 2 * tig + (r & 1);
                float val = acc[mt][nt][r] + bias[n];
                if (MODE == 0) {
                    const int which = n / D_;
                    const int d2 = n - which * D_;
                    const int h = d2 >> 6;
                    const int hi = d2 & 63;
                    const int b = m >> 11;
                    const int s = m & 2047;
                    if (which == 0) {
                        g_q[(((size_t)(b * H_ + h) * S_) + s) * HD_ + hi] =
                            __float2half(val * 0.125f);
                    } else if (which == 1) {
                        g_k[(((size_t)(b * H_ + h) * S_) + s) * HD_ + hi] =
                            __float2half(val);
                    } else {
                        g_v[((size_t)(b * H_ + h) * HD_ + hi) * S_ + s] =
                            __float2half(val);
                    }
                } else {
                    Cout[(size_t)m * N + n] = val;
                }
            }
        }
    }
}

// ---------------------------------------------------------------------------
// Flash attention, fp16 mma m16n8k16. 128 threads (4 warps), Br=64, Bc=64.
// 3-stage cp.async ring, prefetch distance 2, occupancy 4 (16 warps/SM).
// Stage (t+2)%3 was consumed at iter t-1; the iter-t barrier fences reuse.
// ---------------------------------------------------------------------------
__global__ __launch_bounds__(128, 4) void attn_mma()
{
    const int qtile = gridDim.x - 1 - blockIdx.x;   // heavy tiles first
    const int h = blockIdx.y;
    const int b = blockIdx.z;
    const int tid = threadIdx.x;
    const int lane = tid & 31;
    const int wid = tid >> 5;
    const int gid = lane >> 2, tig = lane & 3, l7 = lane & 7;

    const int q0 = qtile * 64;
    const int wrow0 = q0 + wid * 16;

    const uint32_t* qu = (const uint32_t*)(g_q + ((size_t)(b * H_ + h) * S_) * HD_);
    const __half* kb = g_k + ((size_t)(b * H_ + h) * S_) * HD_;
    const __half* vtb = g_v + ((size_t)(b * H_ + h) * HD_) * S_;

    uint32_t qf[4][4];
#pragma unroll
    for (int kk = 0; kk < 4; kk++) {
        const int r0 = wrow0 + gid;
        const int u0 = r0 * 32 + kk * 8 + tig;
        const int u1 = (r0 + 8) * 32 + kk * 8 + tig;
        qf[kk][0] = qu[u0];
        qf[kk][1] = qu[u1];
        qf[kk][2] = qu[u0 + 4];
        qf[kk][3] = qu[u1 + 4];
    }

    float o[8][4];
#pragma unroll
    for (int nt = 0; nt < 8; nt++)
#pragma unroll
        for (int r = 0; r < 4; r++) o[nt][r] = 0.f;
    float m0 = -1e30f, m1 = -1e30f, l0 = 0.f, l1 = 0.f;

    extern __shared__ uint32_t asmem[];   // [3][16KB]: K 8KB + Vt 8KB per stage
    const uint32_t sbase = (uint32_t)__cvta_generic_to_shared(asmem);

    const int row_ = tid >> 3, g_ = tid & 7;
    const uint32_t dofs = (uint32_t)(row_ * 128 + ((g_ ^ (row_ & 7)) * 16));

    auto issueT = [&](int s, int t) {
        const int k0 = t * 64;
        const uint32_t kd = sbase + (uint32_t)(s * 16384) + dofs;
        const uint32_t vd = kd + 8192;
        const __half* kp = kb + (size_t)(k0 + row_) * HD_ + g_ * 8;
        const __half* vp = vtb + (size_t)row_ * S_ + k0 + g_ * 8;
#pragma unroll
        for (int u = 0; u < 4; u++) {
            cp16(kd + u * (16 * 128), kp + (size_t)u * 16 * HD_);
            cp16(vd + u * (16 * 128), vp + (size_t)u * 16 * S_);
        }
    };

    const uint32_t rowbB = (uint32_t)((l7 + ((lane >> 4) & 1) * 8) * 128);
    uint32_t bswz[4];
#pragma unroll
    for (int kk = 0; kk < 4; kk++)
        bswz[kk] = (uint32_t)((((kk * 2 + ((lane >> 3) & 1)) ^ l7)) * 16);

    issueT(0, 0); cp_commit();
    if (qtile >= 1) issueT(1, 1);
    cp_commit();

    int sring = 0;   // stage of tile t
    for (int t = 0; t <= qtile; t++) {
        cp_wait<1>();
        __syncthreads();
        if (t + 2 <= qtile) {
            int s2 = sring + 2; if (s2 >= 3) s2 -= 3;
            issueT(s2, t + 2);
        }
        cp_commit();

        const uint32_t baseK = sbase + (uint32_t)(sring * 16384);
        const uint32_t baseV = baseK + 8192;
        const int k0 = t * 64;

        float sfr[8][4];
#pragma unroll
        for (int nt = 0; nt < 8; nt++)
#pragma unroll
            for (int r = 0; r < 4; r++) sfr[nt][r] = 0.f;
#pragma unroll
        for (int kk = 0; kk < 4; kk++) {
#pragma unroll
            for (int ntp = 0; ntp < 4; ntp++) {
                uint32_t bf[4];
                ldsm4(bf, baseK + ntp * (16 * 128) + rowbB + bswz[kk]);
                mma_f16(sfr[ntp * 2],     qf[kk], bf[0], bf[1], sfr[ntp * 2]);
                mma_f16(sfr[ntp * 2 + 1], qf[kk], bf[2], bf[3], sfr[ntp * 2 + 1]);
            }
        }

        const int r0 = wrow0 + gid;
        const int r1 = r0 + 8;
        if (k0 + 63 > wrow0) {
#pragma unroll
            for (int nt = 0; nt < 8; nt++) {
                int c = k0 + nt * 8 + 2 * tig;
                if (c > r0) sfr[nt][0] = MASKED_BIAS;
                if (c + 1 > r0) sfr[nt][1] = MASKED_BIAS;
                if (c > r1) sfr[nt][2] = MASKED_BIAS;
                if (c + 1 > r1) sfr[nt][3] = MASKED_BIAS;
            }
        }

        float mx0 = -1e30f, mx1 = -1e30f;
#pragma unroll
        for (int nt = 0; nt < 8; nt++) {
            mx0 = fmaxf(mx0, fmaxf(sfr[nt][0], sfr[nt][1]));
            mx1 = fmaxf(mx1, fmaxf(sfr[nt][2], sfr[nt][3]));
        }
        mx0 = fmaxf(mx0, __shfl_xor_sync(0xffffffffu, mx0, 1));
        mx0 = fmaxf(mx0, __shfl_xor_sync(0xffffffffu, mx0, 2));
        mx1 = fmaxf(mx1, __shfl_xor_sync(0xffffffffu, mx1, 1));
        mx1 = fmaxf(mx1, __shfl_xor_sync(0xffffffffu, mx1, 2));

        const float mn0 = fmaxf(m0, mx0);
        const float mn1 = fmaxf(m1, mx1);
        float a0, a1;
        {
            uint32_t sc = ex2h2(packh2((m0 - mn0) * L2E, (m1 - mn1) * L2E));
            float2 scf = __half22float2(*(__half2*)&sc);
            a0 = scf.x; a1 = scf.y;
        }
        m0 = mn0; m1 = mn1;
        const float b0l = m0 * L2E;
        const float b1l = m1 * L2E;

        uint32_t pf[4][4];
#pragma unroll
        for (int nt = 0; nt < 8; nt++) {
            uint32_t ha = packh2(fmaf(sfr[nt][0], L2E, -b0l),
                                 fmaf(sfr[nt][1], L2E, -b0l));
            uint32_t hb = packh2(fmaf(sfr[nt][2], L2E, -b1l),
                                 fmaf(sfr[nt][3], L2E, -b1l));
            pf[nt >> 1][(nt & 1) * 2]     = ex2h2(ha);
            pf[nt >> 1][(nt & 1) * 2 + 1] = ex2h2(hb);
        }

        float ls0 = 0.f, ls1 = 0.f;
#pragma unroll
        for (int kv = 0; kv < 4; kv++) {
            __half2 s0 = __hadd2(*(__half2*)&pf[kv][0], *(__half2*)&pf[kv][2]);
            __half2 s1 = __hadd2(*(__half2*)&pf[kv][1], *(__half2*)&pf[kv][3]);
            float2 f0 = __half22float2(s0);
            float2 f1 = __half22float2(s1);
            ls0 += f0.x + f0.y;
            ls1 += f1.x + f1.y;
        }
        ls0 += __shfl_xor_sync(0xffffffffu, ls0, 1);
        ls0 += __shfl_xor_sync(0xffffffffu, ls0, 2);
        ls1 += __shfl_xor_sync(0xffffffffu, ls1, 1);
        ls1 += __shfl_xor_sync(0xffffffffu, ls1, 2);
        l0 = l0 * a0 + ls0;
        l1 = l1 * a1 + ls1;

#pragma unroll
        for (int nt = 0; nt < 8; nt++) {
            o[nt][0] *= a0; o[nt][1] *= a0;
            o[nt][2] *= a1; o[nt][3] *= a1;
        }

#pragma unroll
        for (int kkv = 0; kkv < 4; kkv++) {
#pragma unroll
            for (int ntp = 0; ntp < 4; ntp++) {
                uint32_t bf[4];
                ldsm4(bf, baseV + ntp * (16 * 128) + rowbB + bswz[kkv]);
                mma_f16(o[ntp * 2],     pf[kkv], bf[0], bf[1], o[ntp * 2]);
                mma_f16(o[ntp * 2 + 1], pf[kkv], bf[2], bf[3], o[ntp * 2 + 1]);
            }
        }

        if (++sring == 3) sring = 0;
    }

    const float inv0 = 1.f / l0;
    const float inv1 = 1.f / l1;
    const int r0 = wrow0 + gid;
    uint32_t* ob0 = (uint32_t*)(g_att + ((size_t)(b * S_ + r0)) * D_ + h * HD_);
    uint32_t* ob1 = (uint32_t*)(g_att + ((size_t)(b * S_ + r0 + 8)) * D_ + h * HD_);
#pragma unroll
    for (int nt = 0; nt < 8; nt++) {
        ob0[nt * 4 + tig] = packh2(o[nt][0] * inv0, o[nt][1] * inv0);
        ob1[nt * 4 + tig] = packh2(o[nt][2] * inv1, o[nt][3] * inv1);
    }
}

// ---------------------------------------------------------------------------
extern "C" void kernel_launch(void* const* d_in, const int* in_sizes, int n_in,
                              void* d_out, int out_size)
{
    const float* hidden   = (const float*)d_in[0];
    const float* c_attn_w = (const float*)d_in[1];
    const float* c_attn_b = (const float*)d_in[2];
    const float* c_proj_w = (const float*)d_in[3];
    const float* c_proj_b = (const float*)d_in[4];
    float* out = (float*)d_out;

    constexpr int SMEM_G128 = 3 * (128 + 128) * 128;   // 96KB
    constexpr int SMEM_G64  = 3 * (128 + 64) * 128;    // 72KB
    constexpr int SMEM_ATTN = 3 * 16384;               // 48KB

    static bool attr_set = false;
    if (!attr_set) {
        cudaFuncSetAttribute((const void*)mma_gemm<0, 128>,
            cudaFuncAttributeMaxDynamicSharedMemorySize, SMEM_G128);
        cudaFuncSetAttribute((const void*)mma_gemm<1, 64>,
            cudaFuncAttributeMaxDynamicSharedMemorySize, SMEM_G64);
        cudaFuncSetAttribute((const void*)attn_mma,
            cudaFuncAttributeMaxDynamicSharedMemorySize, SMEM_ATTN);
        attr_set = true;
    }

    __half *px, *pwq, *pwp, *patt;
    cudaGetSymbolAddress((void**)&px, g_x);
    cudaGetSymbolAddress((void**)&pwq, g_wqkv_t);
    cudaGetSymbolAddress((void**)&pwp, g_wp_t);
    cudaGetSymbolAddress((void**)&patt, g_att);

    // Fused pre-pass (1 launch)
    prepass<<<NB_CVT + NB_TQ + NB_TP, 256>>>(hidden, c_attn_w, c_proj_w);

    // Phase 1: QKV GEMM + head split (+ q scaling, v transpose)
    {
        dim3 grid(N_QKV / 128, M_ / 128);   // (18, 32)
        mma_gemm<0, 128><<<grid, 256, SMEM_G128>>>(px, pwq, c_attn_b, nullptr,
                                                   D_, N_QKV);
    }
    // Phase 2: causal flash attention, Br=64, occ 4
    {
        dim3 grid(S_ / 64, H_, B_);         // (32, 12, 2)
        attn_mma<<<grid, 128, SMEM_ATTN>>>();
    }
    // Phase 3: output projection, BN=64 tiles (R9 config)
    {
        dim3 grid(D_ / 64, M_ / 128);       // (12, 32) = 384 blocks
        mma_gemm<1, 64><<<grid, 256, SMEM_G64>>>(patt, pwp, c_proj_b, out,
                                                 D_, D_);
    }
}

// round 13
// speedup vs baseline: 1.1968x; 1.0988x over previous
#include <cuda_runtime.h>
#include <cuda_fp16.h>
#include <cstdint>

// GPT2 attention block, fp16 mma.sync (m16n8k16, fp32 accum) + cp.async.
// B=2, S=2048, D=768, H=12, hd=64

#define B_ 2
#define S_ 2048
#define D_ 768
#define H_ 12
#define HD_ 64
#define M_ (B_ * S_)        // 4096
#define N_QKV (3 * D_)      // 2304
#define MASKED_BIAS (-10000.0f)
#define L2E 1.4426950408889634f

// Scratch (no cudaMalloc allowed) — all fp16
__device__ __align__(128) __half g_q[B_ * H_ * S_ * HD_];   // [b,h,s,d], pre-scaled 1/8
__device__ __align__(128) __half g_k[B_ * H_ * S_ * HD_];   // [b,h,s,d]
__device__ __align__(128) __half g_v[B_ * H_ * S_ * HD_];   // [b,h,d,s]  (TRANSPOSED)
__device__ __align__(128) __half g_att[M_ * D_];
__device__ __align__(128) __half g_x[M_ * D_];              // hidden fp16
__device__ __align__(128) __half g_wqkv_t[N_QKV * D_];      // [n][k]
__device__ __align__(128) __half g_wp_t[D_ * D_];           // [n][k]

// ---------------------------------------------------------------------------
__device__ __forceinline__ uint32_t packh2(float lo, float hi) {
    __half2 h = __floats2half2_rn(lo, hi);
    return *(uint32_t*)&h;
}
__device__ __forceinline__ uint32_t ex2h2(uint32_t x) {
    uint32_t y;
    asm("ex2.approx.f16x2 %0, %1;" : "=r"(y) : "r"(x));
    return y;
}
__device__ __forceinline__ void mma_f16(float d[4], const uint32_t a[4],
                                        const uint32_t b0, const uint32_t b1,
                                        const float c[4]) {
    asm volatile(
        "mma.sync.aligned.m16n8k16.row.col.f32.f16.f16.f32 "
        "{%0,%1,%2,%3}, {%4,%5,%6,%7}, {%8,%9}, {%10,%11,%12,%13};\n"
        : "=f"(d[0]), "=f"(d[1]), "=f"(d[2]), "=f"(d[3])
        : "r"(a[0]), "r"(a[1]), "r"(a[2]), "r"(a[3]),
          "r"(b0), "r"(b1),
          "f"(c[0]), "f"(c[1]), "f"(c[2]), "f"(c[3]));
}
__device__ __forceinline__ void ldsm4(uint32_t r[4], uint32_t addr) {
    asm volatile("ldmatrix.sync.aligned.m8n8.x4.shared.b16 {%0,%1,%2,%3}, [%4];"
        : "=r"(r[0]), "=r"(r[1]), "=r"(r[2]), "=r"(r[3]) : "r"(addr));
}
__device__ __forceinline__ void cp16(uint32_t dst, const void* src) {
    asm volatile("cp.async.cg.shared.global [%0], [%1], 16;\n"
                 :: "r"(dst), "l"(src));
}
__device__ __forceinline__ void cp_commit() {
    asm volatile("cp.async.commit_group;\n");
}
template <int N>
__device__ __forceinline__ void cp_wait() {
    asm volatile("cp.async.wait_group %0;\n" :: "n"(N));
}

// ---------------------------------------------------------------------------
// Fused pre-pass: one launch does hidden cvt + both weight transposes.
// ---------------------------------------------------------------------------
#define NB_CVT (M_ * D_ / 4 / 256)          // 3072
#define NB_TQ  ((N_QKV / 32) * (D_ / 32))   // 1728
#define NB_TP  ((D_ / 32) * (D_ / 32))      // 576

__global__ __launch_bounds__(256) void prepass(
    const float* __restrict__ hidden,
    const float* __restrict__ wq,
    const float* __restrict__ wp)
{
    const int bid = blockIdx.x;
    const int tid = threadIdx.x;

    if (bid < NB_CVT) {
        int i = bid * 256 + tid;
        float4 v = ((const float4*)hidden)[i];
        uint2 t;
        t.x = packh2(v.x, v.y);
        t.y = packh2(v.z, v.w);
        ((uint2*)g_x)[i] = t;
        return;
    }

    const float* src;
    __half* dst;
    int R, C, bx, by;
    if (bid < NB_CVT + NB_TQ) {
        int bi = bid - NB_CVT;
        src = wq; dst = g_wqkv_t; R = D_; C = N_QKV;
        bx = bi % (N_QKV / 32); by = bi / (N_QKV / 32);
    } else {
        int bi = bid - NB_CVT - NB_TQ;
        src = wp; dst = g_wp_t; R = D_; C = D_;
        bx = bi % (D_ / 32); by = bi / (D_ / 32);
    }

    __shared__ float tile[32][33];
    const int c0 = bx * 32, r0 = by * 32;
    const int x = tid & 31, y = tid >> 5;
#pragma unroll
    for (int j = 0; j < 32; j += 8)
        tile[y + j][x] = src[(size_t)(r0 + y + j) * C + c0 + x];
    __syncthreads();
#pragma unroll
    for (int j = 0; j < 32; j += 8)
        dst[(size_t)(c0 + y + j) * R + r0 + x] = __float2half(tile[x][y + j]);
}

// ---------------------------------------------------------------------------
// FP16 GEMM: 128 x BN_ x 64 tile, THREADS threads, cp.async 3-stage,
// XOR-swizzled smem, ldmatrix. Packed (half2/float2) epilogue stores.
//   GEMM1: MODE 0, BN=128, 256 thr, occ 2.
//   proj : MODE 1, BN= 64, 128 thr, occ 3 (384 blocks = single wave).
// ---------------------------------------------------------------------------
template <int MODE, int BN_, int THREADS, int OCC>
__global__ __launch_bounds__(THREADS, OCC) void mma_gemm(
    const __half* __restrict__ A,   // [M][K]
    const __half* __restrict__ Bt,  // [N][K]
    const float* __restrict__ bias,
    float* __restrict__ Cout,
    int K, int N)
{
    constexpr int BM = 128, BN = BN_, BK = 64;            // BK in halfs (128B)
    constexpr int STAGE_BYTES = (BM + BN) * 128;
    constexpr int NWARPS = THREADS / 32;
    constexpr int WN_CNT = BN / 32;
    constexpr int WM_CNT = NWARPS / WN_CNT;
    constexpr int MT = 128 / (WM_CNT * 16);
    constexpr int ROWS_PASS = THREADS / 8;
    constexpr int APASS = BM / ROWS_PASS;
    constexpr int BPASS = BN / ROWS_PASS;

    extern __shared__ uint32_t smem[];
    const uint32_t sbase = (uint32_t)__cvta_generic_to_shared(smem);

    const int tid = threadIdx.x;
    const int lane = tid & 31;
    const int wid = tid >> 5;
    const int wm = wid % WM_CNT, wn = wid / WM_CNT;
    const int gid = lane >> 2, tig = lane & 3, l7 = lane & 7;
    const int bm = blockIdx.y, bn = blockIdx.x;

    const int row_ = tid >> 3, g_ = tid & 7;
    const __half* asrc = A + (size_t)(bm * BM + row_) * K + g_ * 8;
    const __half* bsrc = Bt + (size_t)(bn * BN + row_) * K + g_ * 8;
    const uint32_t dofs = (uint32_t)(row_ * 128 + ((g_ ^ (row_ & 7)) * 16));

    auto issue = [&](int s, int kt) {
        const uint32_t sb = sbase + (uint32_t)(s * STAGE_BYTES);
        const __half* ap = asrc + kt * BK;
        const __half* bp = bsrc + kt * BK;
        const uint32_t ad = sb + dofs;
        const uint32_t bd = ad + (uint32_t)(BM * 128);
#pragma unroll
        for (int u = 0; u < APASS; u++)
            cp16(ad + u * (ROWS_PASS * 128), ap + (size_t)u * ROWS_PASS * K);
#pragma unroll
        for (int u = 0; u < BPASS; u++)
            cp16(bd + u * (ROWS_PASS * 128), bp + (size_t)u * ROWS_PASS * K);
    };

    const uint32_t arowb =
        (uint32_t)((wm * (MT * 16) + l7 + ((lane >> 3) & 1) * 8) * 128);
    const uint32_t browb =
        (uint32_t)((wn * 32 + l7 + ((lane >> 4) & 1) * 8) * 128)
        + (uint32_t)(BM * 128);
    uint32_t aswz[4], bswz[4];
#pragma unroll
    for (int kk = 0; kk < 4; kk++) {
        aswz[kk] = (uint32_t)((((kk * 2 + (lane >> 4)) ^ l7)) * 16);
        bswz[kk] = (uint32_t)((((kk * 2 + ((lane >> 3) & 1)) ^ l7)) * 16);
    }

    float acc[MT][4][4];
#pragma unroll
    for (int i = 0; i < MT; i++)
#pragma unroll
        for (int j = 0; j < 4; j++)
#pragma unroll
            for (int r = 0; r < 4; r++) acc[i][j][r] = 0.f;

    issue(0, 0); cp_commit();
    issue(1, 1); cp_commit();

    const int ksteps = K / BK;   // 12
    int st = 0;
    for (int kt = 0; kt < ksteps; kt++) {
        cp_wait<1>();
        __syncthreads();
        if (kt + 2 < ksteps) {
            int s2 = st + 2; if (s2 >= 3) s2 -= 3;
            issue(s2, kt + 2);
        }
        cp_commit();

        const uint32_t sb = sbase + (uint32_t)(st * STAGE_BYTES);
#pragma unroll
        for (int kk = 0; kk < 4; kk++) {
            uint32_t bf[2][4];
#pragma unroll
            for (int ntp = 0; ntp < 2; ntp++)
                ldsm4(bf[ntp], sb + browb + ntp * (16 * 128) + bswz[kk]);
            uint32_t af[MT][4];
#pragma unroll
            for (int mt = 0; mt < MT; mt++)
                ldsm4(af[mt], sb + arowb + mt * (16 * 128) + aswz[kk]);
#pragma unroll
            for (int mt = 0; mt < MT; mt++)
#pragma unroll
                for (int ntp = 0; ntp < 2; ntp++) {
                    mma_f16(acc[mt][ntp * 2],     af[mt], bf[ntp][0], bf[ntp][1],
                            acc[mt][ntp * 2]);
                    mma_f16(acc[mt][ntp * 2 + 1], af[mt], bf[ntp][2], bf[ntp][3],
                            acc[mt][ntp * 2 + 1]);
                }
        }
        if (++st == 3) st = 0;
    }

    // ---- epilogue: packed stores (n0 = even, pair (n0, n0+1)) ----
#pragma unroll
    for (int mt = 0; mt < MT; mt++) {
#pragma unroll
        for (int nt = 0; nt < 4; nt++) {
            const int n0 = bn * BN + wn * 32 + nt * 8 + 2 * tig;
            const float bz0 = bias[n0], bz1 = bias[n0 + 1];
            const int m0 = bm * BM + wm * (MT * 16) + mt * 16 + gid;
            const int m1 = m0 + 8;
            const float v00 = acc[mt][nt][0] + bz0;
            const float v01 = acc[mt][nt][1] + bz1;
            const float v10 = acc[mt][nt][2] + bz0;
            const float v11 = acc[mt][nt][3] + bz1;
            if (MODE == 0) {
                const int which = n0 / D_;
                const int d2 = n0 - which * D_;
                const int h = d2 >> 6;
                const int hi = d2 & 63;   // even, hi+1 in same head
                const int b0 = m0 >> 11, s0 = m0 & 2047;
                const int b1 = m1 >> 11, s1 = m1 & 2047;
                if (which == 0) {
                    *(uint32_t*)&g_q[(((size_t)(b0 * H_ + h) * S_) + s0) * HD_ + hi] =
                        packh2(v00 * 0.125f, v01 * 0.125f);
                    *(uint32_t*)&g_q[(((size_t)(b1 * H_ + h) * S_) + s1) * HD_ + hi] =
                        packh2(v10 * 0.125f, v11 * 0.125f);
                } else if (which == 1) {
                    *(uint32_t*)&g_k[(((size_t)(b0 * H_ + h) * S_) + s0) * HD_ + hi] =
                        packh2(v00, v01);
                    *(uint32_t*)&g_k[(((size_t)(b1 * H_ + h) * S_) + s1) * HD_ + hi] =
                        packh2(v10, v11);
                } else {
                    __half* vb0 = &g_v[((size_t)(b0 * H_ + h) * HD_ + hi) * S_];
                    __half* vb1 = &g_v[((size_t)(b1 * H_ + h) * HD_ + hi) * S_];
                    vb0[s0] = __float2half(v00);
                    vb0[S_ + s0] = __float2half(v01);
                    vb1[s1] = __float2half(v10);
                    vb1[S_ + s1] = __float2half(v11);
                }
            } else {
                *(float2*)&Cout[(size_t)m0 * N + n0] = make_float2(v00, v01);
                *(float2*)&Cout[(size_t)m1 * N + n0] = make_float2(v10, v11);
            }
        }
    }
}

// ---------------------------------------------------------------------------
// Flash attention, fp16 mma m16n8k16. 128 threads (4 warps), Br=64, Bc=64.
// 3-stage cp.async ring, prefetch distance 2, occupancy 4 (16 warps/SM).
// ---------------------------------------------------------------------------
__global__ __launch_bounds__(128, 4) void attn_mma()
{
    const int qtile = gridDim.x - 1 - blockIdx.x;   // heavy tiles first
    const int h = blockIdx.y;
    const int b = blockIdx.z;
    const int tid = threadIdx.x;
    const int lane = tid & 31;
    const int wid = tid >> 5;
    const int gid = lane >> 2, tig = lane & 3, l7 = lane & 7;

    const int q0 = qtile * 64;
    const int wrow0 = q0 + wid * 16;

    const uint32_t* qu = (const uint32_t*)(g_q + ((size_t)(b * H_ + h) * S_) * HD_);
    const __half* kb = g_k + ((size_t)(b * H_ + h) * S_) * HD_;
    const __half* vtb = g_v + ((size_t)(b * H_ + h) * HD_) * S_;

    uint32_t qf[4][4];
#pragma unroll
    for (int kk = 0; kk < 4; kk++) {
        const int r0 = wrow0 + gid;
        const int u0 = r0 * 32 + kk * 8 + tig;
        const int u1 = (r0 + 8) * 32 + kk * 8 + tig;
        qf[kk][0] = qu[u0];
        qf[kk][1] = qu[u1];
        qf[kk][2] = qu[u0 + 4];
        qf[kk][3] = qu[u1 + 4];
    }

    float o[8][4];
#pragma unroll
    for (int nt = 0; nt < 8; nt++)
#pragma unroll
        for (int r = 0; r < 4; r++) o[nt][r] = 0.f;
    float m0 = -1e30f, m1 = -1e30f, l0 = 0.f, l1 = 0.f;

    extern __shared__ uint32_t asmem[];   // [3][16KB]: K 8KB + Vt 8KB per stage
    const uint32_t sbase = (uint32_t)__cvta_generic_to_shared(asmem);

    const int row_ = tid >> 3, g_ = tid & 7;
    const uint32_t dofs = (uint32_t)(row_ * 128 + ((g_ ^ (row_ & 7)) * 16));

    auto issueT = [&](int s, int t) {
        const int k0 = t * 64;
        const uint32_t kd = sbase + (uint32_t)(s * 16384) + dofs;
        const uint32_t vd = kd + 8192;
        const __half* kp = kb + (size_t)(k0 + row_) * HD_ + g_ * 8;
        const __half* vp = vtb + (size_t)row_ * S_ + k0 + g_ * 8;
#pragma unroll
        for (int u = 0; u < 4; u++) {
            cp16(kd + u * (16 * 128), kp + (size_t)u * 16 * HD_);
            cp16(vd + u * (16 * 128), vp + (size_t)u * 16 * S_);
        }
    };

    const uint32_t rowbB = (uint32_t)((l7 + ((lane >> 4) & 1) * 8) * 128);
    uint32_t bswz[4];
#pragma unroll
    for (int kk = 0; kk < 4; kk++)
        bswz[kk] = (uint32_t)((((kk * 2 + ((lane >> 3) & 1)) ^ l7)) * 16);

    issueT(0, 0); cp_commit();
    if (qtile >= 1) issueT(1, 1);
    cp_commit();

    int sring = 0;
    for (int t = 0; t <= qtile; t++) {
        cp_wait<1>();
        __syncthreads();
        if (t + 2 <= qtile) {
            int s2 = sring + 2; if (s2 >= 3) s2 -= 3;
            issueT(s2, t + 2);
        }
        cp_commit();

        const uint32_t baseK = sbase + (uint32_t)(sring * 16384);
        const uint32_t baseV = baseK + 8192;
        const int k0 = t * 64;

        float sfr[8][4];
#pragma unroll
        for (int nt = 0; nt < 8; nt++)
#pragma unroll
            for (int r = 0; r < 4; r++) sfr[nt][r] = 0.f;
#pragma unroll
        for (int kk = 0; kk < 4; kk++) {
#pragma unroll
            for (int ntp = 0; ntp < 4; ntp++) {
                uint32_t bf[4];
                ldsm4(bf, baseK + ntp * (16 * 128) + rowbB + bswz[kk]);
                mma_f16(sfr[ntp * 2],     qf[kk], bf[0], bf[1], sfr[ntp * 2]);
                mma_f16(sfr[ntp * 2 + 1], qf[kk], bf[2], bf[3], sfr[ntp * 2 + 1]);
            }
        }

        const int r0 = wrow0 + gid;
        const int r1 = r0 + 8;
        if (k0 + 63 > wrow0) {
#pragma unroll
            for (int nt = 0; nt < 8; nt++) {
                int c = k0 + nt * 8 + 2 * tig;
                if (c > r0) sfr[nt][0] = MASKED_BIAS;
                if (c + 1 > r0) sfr[nt][1] = MASKED_BIAS;
                if (c > r1) sfr[nt][2] = MASKED_BIAS;
                if (c + 1 > r1) sfr[nt][3] = MASKED_BIAS;
            }
        }

        float mx0 = -1e30f, mx1 = -1e30f;
#pragma unroll
        for (int nt = 0; nt < 8; nt++) {
            mx0 = fmaxf(mx0, fmaxf(sfr[nt][0], sfr[nt][1]));
            mx1 = fmaxf(mx1, fmaxf(sfr[nt][2], sfr[nt][3]));
        }
        mx0 = fmaxf(mx0, __shfl_xor_sync(0xffffffffu, mx0, 1));
        mx0 = fmaxf(mx0, __shfl_xor_sync(0xffffffffu, mx0, 2));
        mx1 = fmaxf(mx1, __shfl_xor_sync(0xffffffffu, mx1, 1));
        mx1 = fmaxf(mx1, __shfl_xor_sync(0xffffffffu, mx1, 2));

        const float mn0 = fmaxf(m0, mx0);
        const float mn1 = fmaxf(m1, mx1);
        float a0, a1;
        {
            uint32_t sc = ex2h2(packh2((m0 - mn0) * L2E, (m1 - mn1) * L2E));
            float2 scf = __half22float2(*(__half2*)&sc);
            a0 = scf.x; a1 = scf.y;
        }
        m0 = mn0; m1 = mn1;
        const float b0l = m0 * L2E;
        const float b1l = m1 * L2E;

        uint32_t pf[4][4];
#pragma unroll
        for (int nt = 0; nt < 8; nt++) {
            uint32_t ha = packh2(fmaf(sfr[nt][0], L2E, -b0l),
                                 fmaf(sfr[nt][1], L2E, -b0l));
            uint32_t hb = packh2(fmaf(sfr[nt][2], L2E, -b1l),
                                 fmaf(sfr[nt][3], L2E, -b1l));
            pf[nt >> 1][(nt & 1) * 2]     = ex2h2(ha);
            pf[nt >> 1][(nt & 1) * 2 + 1] = ex2h2(hb);
        }

        float ls0 = 0.f, ls1 = 0.f;
#pragma unroll
        for (int kv = 0; kv < 4; kv++) {
            __half2 s0 = __hadd2(*(__half2*)&pf[kv][0], *(__half2*)&pf[kv][2]);
            __half2 s1 = __hadd2(*(__half2*)&pf[kv][1], *(__half2*)&pf[kv][3]);
            float2 f0 = __half22float2(s0);
            float2 f1 = __half22float2(s1);
            ls0 += f0.x + f0.y;
            ls1 += f1.x + f1.y;
        }
        ls0 += __shfl_xor_sync(0xffffffffu, ls0, 1);
        ls0 += __shfl_xor_sync(0xffffffffu, ls0, 2);
        ls1 += __shfl_xor_sync(0xffffffffu, ls1, 1);
        ls1 += __shfl_xor_sync(0xffffffffu, ls1, 2);
        l0 = l0 * a0 + ls0;
        l1 = l1 * a1 + ls1;

#pragma unroll
        for (int nt = 0; nt < 8; nt++) {
            o[nt][0] *= a0; o[nt][1] *= a0;
            o[nt][2] *= a1; o[nt][3] *= a1;
        }

#pragma unroll
        for (int kkv = 0; kkv < 4; kkv++) {
#pragma unroll
            for (int ntp = 0; ntp < 4; ntp++) {
                uint32_t bf[4];
                ldsm4(bf, baseV + ntp * (16 * 128) + rowbB + bswz[kkv]);
                mma_f16(o[ntp * 2],     pf[kkv], bf[0], bf[1], o[ntp * 2]);
                mma_f16(o[ntp * 2 + 1], pf[kkv], bf[2], bf[3], o[ntp * 2 + 1]);
            }
        }

        if (++sring == 3) sring = 0;
    }

    const float inv0 = 1.f / l0;
    const float inv1 = 1.f / l1;
    const int r0 = wrow0 + gid;
    uint32_t* ob0 = (uint32_t*)(g_att + ((size_t)(b * S_ + r0)) * D_ + h * HD_);
    uint32_t* ob1 = (uint32_t*)(g_att + ((size_t)(b * S_ + r0 + 8)) * D_ + h * HD_);
#pragma unroll
    for (int nt = 0; nt < 8; nt++) {
        ob0[nt * 4 + tig] = packh2(o[nt][0] * inv0, o[nt][1] * inv0);
        ob1[nt * 4 + tig] = packh2(o[nt][2] * inv1, o[nt][3] * inv1);
    }
}

// ---------------------------------------------------------------------------
extern "C" void kernel_launch(void* const* d_in, const int* in_sizes, int n_in,
                              void* d_out, int out_size)
{
    const float* hidden   = (const float*)d_in[0];
    const float* c_attn_w = (const float*)d_in[1];
    const float* c_attn_b = (const float*)d_in[2];
    const float* c_proj_w = (const float*)d_in[3];
    const float* c_proj_b = (const float*)d_in[4];
    float* out = (float*)d_out;

    constexpr int SMEM_G128 = 3 * (128 + 128) * 128;   // 96KB
    constexpr int SMEM_G64  = 3 * (128 + 64) * 128;    // 72KB
    constexpr int SMEM_ATTN = 3 * 16384;               // 48KB

    static bool attr_set = false;
    if (!attr_set) {
        cudaFuncSetAttribute((const void*)mma_gemm<0, 128, 256, 2>,
            cudaFuncAttributeMaxDynamicSharedMemorySize, SMEM_G128);
        cudaFuncSetAttribute((const void*)mma_gemm<1, 64, 128, 3>,
            cudaFuncAttributeMaxDynamicSharedMemorySize, SMEM_G64);
        cudaFuncSetAttribute((const void*)attn_mma,
            cudaFuncAttributeMaxDynamicSharedMemorySize, SMEM_ATTN);
        attr_set = true;
    }

    __half *px, *pwq, *pwp, *patt;
    cudaGetSymbolAddress((void**)&px, g_x);
    cudaGetSymbolAddress((void**)&pwq, g_wqkv_t);
    cudaGetSymbolAddress((void**)&pwp, g_wp_t);
    cudaGetSymbolAddress((void**)&patt, g_att);

    // Fused pre-pass (1 launch)
    prepass<<<NB_CVT + NB_TQ + NB_TP, 256>>>(hidden, c_attn_w, c_proj_w);

    // Phase 1: QKV GEMM + head split (+ q scaling, v transpose)
    {
        dim3 grid(N_QKV / 128, M_ / 128);   // (18, 32)
        mma_gemm<0, 128, 256, 2><<<grid, 256, SMEM_G128>>>(
            px, pwq, c_attn_b, nullptr, D_, N_QKV);
    }
    // Phase 2: causal flash attention, Br=64, occ 4
    {
        dim3 grid(S_ / 64, H_, B_);         // (32, 12, 2)
        attn_mma<<<grid, 128, SMEM_ATTN>>>();
    }
    // Phase 3: output projection — 128-thr CTAs, occ 3 -> 384 blocks, 1 wave
    {
        dim3 grid(D_ / 64, M_ / 128);       // (12, 32)
        mma_gemm<1, 64, 128, 3><<<grid, 128, SMEM_G64>>>(
            patt, pwp, c_proj_b, out, D_, D_);
    }
}

// round 14
// speedup vs baseline: 1.2159x; 1.0159x over previous
#include <cuda_runtime.h>
#include <cuda_fp16.h>
#include <cstdint>

// GPT2 attention block, fp16 mma.sync (m16n8k16, fp32 accum) + cp.async.
// B=2, S=2048, D=768, H=12, hd=64

#define B_ 2
#define S_ 2048
#define D_ 768
#define H_ 12
#define HD_ 64
#define M_ (B_ * S_)        // 4096
#define N_QKV (3 * D_)      // 2304
#define MASKED_BIAS (-10000.0f)
#define L2E 1.4426950408889634f

// Scratch (no cudaMalloc allowed) — all fp16
__device__ __align__(128) __half g_q[B_ * H_ * S_ * HD_];   // [b,h,s,d], pre-scaled 1/8
__device__ __align__(128) __half g_k[B_ * H_ * S_ * HD_];   // [b,h,s,d]
__device__ __align__(128) __half g_v[B_ * H_ * S_ * HD_];   // [b,h,d,s]  (TRANSPOSED)
__device__ __align__(128) __half g_att[M_ * D_];
__device__ __align__(128) __half g_x[M_ * D_];              // hidden fp16
__device__ __align__(128) __half g_wqkv_t[N_QKV * D_];      // [n][k]
__device__ __align__(128) __half g_wp_t[D_ * D_];           // [n][k]

// ---------------------------------------------------------------------------
__device__ __forceinline__ uint32_t packh2(float lo, float hi) {
    __half2 h = __floats2half2_rn(lo, hi);
    return *(uint32_t*)&h;
}
__device__ __forceinline__ uint32_t ex2h2(uint32_t x) {
    uint32_t y;
    asm("ex2.approx.f16x2 %0, %1;" : "=r"(y) : "r"(x));
    return y;
}
__device__ __forceinline__ void mma_f16(float d[4], const uint32_t a[4],
                                        const uint32_t b0, const uint32_t b1,
                                        const float c[4]) {
    asm volatile(
        "mma.sync.aligned.m16n8k16.row.col.f32.f16.f16.f32 "
        "{%0,%1,%2,%3}, {%4,%5,%6,%7}, {%8,%9}, {%10,%11,%12,%13};\n"
        : "=f"(d[0]), "=f"(d[1]), "=f"(d[2]), "=f"(d[3])
        : "r"(a[0]), "r"(a[1]), "r"(a[2]), "r"(a[3]),
          "r"(b0), "r"(b1),
          "f"(c[0]), "f"(c[1]), "f"(c[2]), "f"(c[3]));
}
__device__ __forceinline__ void ldsm4(uint32_t r[4], uint32_t addr) {
    asm volatile("ldmatrix.sync.aligned.m8n8.x4.shared.b16 {%0,%1,%2,%3}, [%4];"
        : "=r"(r[0]), "=r"(r[1]), "=r"(r[2]), "=r"(r[3]) : "r"(addr));
}
__device__ __forceinline__ void cp16(uint32_t dst, const void* src) {
    asm volatile("cp.async.cg.shared.global [%0], [%1], 16;\n"
                 :: "r"(dst), "l"(src));
}
__device__ __forceinline__ void cp_commit() {
    asm volatile("cp.async.commit_group;\n");
}
template <int N>
__device__ __forceinline__ void cp_wait() {
    asm volatile("cp.async.wait_group %0;\n" :: "n"(N));
}

// ---------------------------------------------------------------------------
// Fused pre-pass: one launch does hidden cvt + both weight transposes.
// ---------------------------------------------------------------------------
#define NB_CVT (M_ * D_ / 4 / 256)          // 3072
#define NB_TQ  ((N_QKV / 32) * (D_ / 32))   // 1728
#define NB_TP  ((D_ / 32) * (D_ / 32))      // 576

__global__ __launch_bounds__(256) void prepass(
    const float* __restrict__ hidden,
    const float* __restrict__ wq,
    const float* __restrict__ wp)
{
    const int bid = blockIdx.x;
    const int tid = threadIdx.x;

    if (bid < NB_CVT) {
        int i = bid * 256 + tid;
        float4 v = ((const float4*)hidden)[i];
        uint2 t;
        t.x = packh2(v.x, v.y);
        t.y = packh2(v.z, v.w);
        ((uint2*)g_x)[i] = t;
        return;
    }

    const float* src;
    __half* dst;
    int R, C, bx, by;
    if (bid < NB_CVT + NB_TQ) {
        int bi = bid - NB_CVT;
        src = wq; dst = g_wqkv_t; R = D_; C = N_QKV;
        bx = bi % (N_QKV / 32); by = bi / (N_QKV / 32);
    } else {
        int bi = bid - NB_CVT - NB_TQ;
        src = wp; dst = g_wp_t; R = D_; C = D_;
        bx = bi % (D_ / 32); by = bi / (D_ / 32);
    }

    __shared__ float tile[32][33];
    const int c0 = bx * 32, r0 = by * 32;
    const int x = tid & 31, y = tid >> 5;
#pragma unroll
    for (int j = 0; j < 32; j += 8)
        tile[y + j][x] = src[(size_t)(r0 + y + j) * C + c0 + x];
    __syncthreads();
#pragma unroll
    for (int j = 0; j < 32; j += 8)
        dst[(size_t)(c0 + y + j) * R + r0 + x] = __float2half(tile[x][y + j]);
}

// ---------------------------------------------------------------------------
// FP16 GEMM: 128 x BN_ x 64 tile, THREADS threads, cp.async 3-stage,
// XOR-swizzled smem, ldmatrix. Packed (half2/float2) epilogue stores.
//   GEMM1: MODE 0, BN=128, 256 thr, occ 2.
//   proj : MODE 1, BN= 64, 128 thr, occ 3 (384 blocks = single wave).
// ---------------------------------------------------------------------------
template <int MODE, int BN_, int THREADS, int OCC>
__global__ __launch_bounds__(THREADS, OCC) void mma_gemm(
    const __half* __restrict__ A,   // [M][K]
    const __half* __restrict__ Bt,  // [N][K]
    const float* __restrict__ bias,
    float* __restrict__ Cout,
    int K, int N)
{
    constexpr int BM = 128, BN = BN_, BK = 64;            // BK in halfs (128B)
    constexpr int STAGE_BYTES = (BM + BN) * 128;
    constexpr int NWARPS = THREADS / 32;
    constexpr int WN_CNT = BN / 32;
    constexpr int WM_CNT = NWARPS / WN_CNT;
    constexpr int MT = 128 / (WM_CNT * 16);
    constexpr int ROWS_PASS = THREADS / 8;
    constexpr int APASS = BM / ROWS_PASS;
    constexpr int BPASS = BN / ROWS_PASS;

    extern __shared__ uint32_t smem[];
    const uint32_t sbase = (uint32_t)__cvta_generic_to_shared(smem);

    const int tid = threadIdx.x;
    const int lane = tid & 31;
    const int wid = tid >> 5;
    const int wm = wid % WM_CNT, wn = wid / WM_CNT;
    const int gid = lane >> 2, tig = lane & 3, l7 = lane & 7;
    const int bm = blockIdx.y, bn = blockIdx.x;

    const int row_ = tid >> 3, g_ = tid & 7;
    const __half* asrc = A + (size_t)(bm * BM + row_) * K + g_ * 8;
    const __half* bsrc = Bt + (size_t)(bn * BN + row_) * K + g_ * 8;
    const uint32_t dofs = (uint32_t)(row_ * 128 + ((g_ ^ (row_ & 7)) * 16));

    auto issue = [&](int s, int kt) {
        const uint32_t sb = sbase + (uint32_t)(s * STAGE_BYTES);
        const __half* ap = asrc + kt * BK;
        const __half* bp = bsrc + kt * BK;
        const uint32_t ad = sb + dofs;
        const uint32_t bd = ad + (uint32_t)(BM * 128);
#pragma unroll
        for (int u = 0; u < APASS; u++)
            cp16(ad + u * (ROWS_PASS * 128), ap + (size_t)u * ROWS_PASS * K);
#pragma unroll
        for (int u = 0; u < BPASS; u++)
            cp16(bd + u * (ROWS_PASS * 128), bp + (size_t)u * ROWS_PASS * K);
    };

    const uint32_t arowb =
        (uint32_t)((wm * (MT * 16) + l7 + ((lane >> 3) & 1) * 8) * 128);
    const uint32_t browb =
        (uint32_t)((wn * 32 + l7 + ((lane >> 4) & 1) * 8) * 128)
        + (uint32_t)(BM * 128);
    uint32_t aswz[4], bswz[4];
#pragma unroll
    for (int kk = 0; kk < 4; kk++) {
        aswz[kk] = (uint32_t)((((kk * 2 + (lane >> 4)) ^ l7)) * 16);
        bswz[kk] = (uint32_t)((((kk * 2 + ((lane >> 3) & 1)) ^ l7)) * 16);
    }

    float acc[MT][4][4];
#pragma unroll
    for (int i = 0; i < MT; i++)
#pragma unroll
        for (int j = 0; j < 4; j++)
#pragma unroll
            for (int r = 0; r < 4; r++) acc[i][j][r] = 0.f;

    issue(0, 0); cp_commit();
    issue(1, 1); cp_commit();

    const int ksteps = K / BK;   // 12
    int st = 0;
    for (int kt = 0; kt < ksteps; kt++) {
        cp_wait<1>();
        __syncthreads();
        if (kt + 2 < ksteps) {
            int s2 = st + 2; if (s2 >= 3) s2 -= 3;
            issue(s2, kt + 2);
        }
        cp_commit();

        const uint32_t sb = sbase + (uint32_t)(st * STAGE_BYTES);
#pragma unroll
        for (int kk = 0; kk < 4; kk++) {
            uint32_t bf[2][4];
#pragma unroll
            for (int ntp = 0; ntp < 2; ntp++)
                ldsm4(bf[ntp], sb + browb + ntp * (16 * 128) + bswz[kk]);
            uint32_t af[MT][4];
#pragma unroll
            for (int mt = 0; mt < MT; mt++)
                ldsm4(af[mt], sb + arowb + mt * (16 * 128) + aswz[kk]);
#pragma unroll
            for (int mt = 0; mt < MT; mt++)
#pragma unroll
                for (int ntp = 0; ntp < 2; ntp++) {
                    mma_f16(acc[mt][ntp * 2],     af[mt], bf[ntp][0], bf[ntp][1],
                            acc[mt][ntp * 2]);
                    mma_f16(acc[mt][ntp * 2 + 1], af[mt], bf[ntp][2], bf[ntp][3],
                            acc[mt][ntp * 2 + 1]);
                }
        }
        if (++st == 3) st = 0;
    }

    // ---- epilogue: packed stores (n0 = even, pair (n0, n0+1)) ----
#pragma unroll
    for (int mt = 0; mt < MT; mt++) {
#pragma unroll
        for (int nt = 0; nt < 4; nt++) {
            const int n0 = bn * BN + wn * 32 + nt * 8 + 2 * tig;
            const float bz0 = bias[n0], bz1 = bias[n0 + 1];
            const int m0 = bm * BM + wm * (MT * 16) + mt * 16 + gid;
            const int m1 = m0 + 8;
            const float v00 = acc[mt][nt][0] + bz0;
            const float v01 = acc[mt][nt][1] + bz1;
            const float v10 = acc[mt][nt][2] + bz0;
            const float v11 = acc[mt][nt][3] + bz1;
            if (MODE == 0) {
                const int which = n0 / D_;
                const int d2 = n0 - which * D_;
                const int h = d2 >> 6;
                const int hi = d2 & 63;
                const int b0 = m0 >> 11, s0 = m0 & 2047;
                const int b1 = m1 >> 11, s1 = m1 & 2047;
                if (which == 0) {
                    *(uint32_t*)&g_q[(((size_t)(b0 * H_ + h) * S_) + s0) * HD_ + hi] =
                        packh2(v00 * 0.125f, v01 * 0.125f);
                    *(uint32_t*)&g_q[(((size_t)(b1 * H_ + h) * S_) + s1) * HD_ + hi] =
                        packh2(v10 * 0.125f, v11 * 0.125f);
                } else if (which == 1) {
                    *(uint32_t*)&g_k[(((size_t)(b0 * H_ + h) * S_) + s0) * HD_ + hi] =
                        packh2(v00, v01);
                    *(uint32_t*)&g_k[(((size_t)(b1 * H_ + h) * S_) + s1) * HD_ + hi] =
                        packh2(v10, v11);
                } else {
                    __half* vb0 = &g_v[((size_t)(b0 * H_ + h) * HD_ + hi) * S_];
                    __half* vb1 = &g_v[((size_t)(b1 * H_ + h) * HD_ + hi) * S_];
                    vb0[s0] = __float2half(v00);
                    vb0[S_ + s0] = __float2half(v01);
                    vb1[s1] = __float2half(v10);
                    vb1[S_ + s1] = __float2half(v11);
                }
            } else {
                *(float2*)&Cout[(size_t)m0 * N + n0] = make_float2(v00, v01);
                *(float2*)&Cout[(size_t)m1 * N + n0] = make_float2(v10, v11);
            }
        }
    }
}

// ---------------------------------------------------------------------------
// Flash attention, fp16 mma m16n8k16. 128 threads (4 warps), Br=64, Bc=128
// (two 64-key subtiles sharing ONE online-softmax update per 128 keys).
// 2-stage cp.async double buffer (32KB/stage). occ 3.
// ---------------------------------------------------------------------------
__global__ __launch_bounds__(128, 3) void attn_mma()
{
    const int qtile = gridDim.x - 1 - blockIdx.x;   // heavy tiles first
    const int h = blockIdx.y;
    const int b = blockIdx.z;
    const int tid = threadIdx.x;
    const int lane = tid & 31;
    const int wid = tid >> 5;
    const int gid = lane >> 2, tig = lane & 3, l7 = lane & 7;

    const int q0 = qtile * 64;
    const int wrow0 = q0 + wid * 16;
    const int ntiles = qtile / 2 + 1;     // 128-key tiles (tail masked by causal)

    const uint32_t* qu = (const uint32_t*)(g_q + ((size_t)(b * H_ + h) * S_) * HD_);
    const __half* kb = g_k + ((size_t)(b * H_ + h) * S_) * HD_;
    const __half* vtb = g_v + ((size_t)(b * H_ + h) * HD_) * S_;

    uint32_t qf[4][4];
#pragma unroll
    for (int kk = 0; kk < 4; kk++) {
        const int r0 = wrow0 + gid;
        const int u0 = r0 * 32 + kk * 8 + tig;
        const int u1 = (r0 + 8) * 32 + kk * 8 + tig;
        qf[kk][0] = qu[u0];
        qf[kk][1] = qu[u1];
        qf[kk][2] = qu[u0 + 4];
        qf[kk][3] = qu[u1 + 4];
    }

    float o[8][4];
#pragma unroll
    for (int nt = 0; nt < 8; nt++)
#pragma unroll
        for (int r = 0; r < 4; r++) o[nt][r] = 0.f;
    float m0 = -1e30f, m1 = -1e30f, l0 = 0.f, l1 = 0.f;

    // [2 stages][K0 8KB | V0 8KB | K1 8KB | V1 8KB] = 2 x 32KB
    extern __shared__ uint32_t asmem[];
    const uint32_t sbase = (uint32_t)__cvta_generic_to_shared(asmem);

    const int row_ = tid >> 3, g_ = tid & 7;
    const uint32_t dofs = (uint32_t)(row_ * 128 + ((g_ ^ (row_ & 7)) * 16));

    auto issueT = [&](int s, int t) {
#pragma unroll
        for (int sb = 0; sb < 2; sb++) {
            const int k0 = t * 128 + sb * 64;
            const uint32_t kd = sbase + (uint32_t)(s * 32768 + sb * 16384) + dofs;
            const uint32_t vd = kd + 8192;
            const __half* kp = kb + (size_t)(k0 + row_) * HD_ + g_ * 8;
            const __half* vp = vtb + (size_t)row_ * S_ + k0 + g_ * 8;
#pragma unroll
            for (int u = 0; u < 4; u++) {
                cp16(kd + u * (16 * 128), kp + (size_t)u * 16 * HD_);
                cp16(vd + u * (16 * 128), vp + (size_t)u * 16 * S_);
            }
        }
    };

    const uint32_t rowbB = (uint32_t)((l7 + ((lane >> 4) & 1) * 8) * 128);
    uint32_t bswz[4];
#pragma unroll
    for (int kk = 0; kk < 4; kk++)
        bswz[kk] = (uint32_t)((((kk * 2 + ((lane >> 3) & 1)) ^ l7)) * 16);

    issueT(0, 0); cp_commit();

    for (int t = 0; t < ntiles; t++) {
        cp_wait<0>();
        __syncthreads();
        if (t + 1 < ntiles) {
            issueT((t + 1) & 1, t + 1);
            cp_commit();
        }

        const uint32_t base = sbase + (uint32_t)((t & 1) * 32768);
        const int k0t = t * 128;

        // ---- S = Q @ K^T over 128 keys (two 64-key subtiles) ----
        float sfr[16][4];
#pragma unroll
        for (int j = 0; j < 16; j++)
#pragma unroll
            for (int r = 0; r < 4; r++) sfr[j][r] = 0.f;
#pragma unroll
        for (int sb = 0; sb < 2; sb++) {
            const uint32_t baseK = base + sb * 16384;
#pragma unroll
            for (int kk = 0; kk < 4; kk++) {
#pragma unroll
                for (int ntp = 0; ntp < 4; ntp++) {
                    uint32_t bf[4];
                    ldsm4(bf, baseK + ntp * (16 * 128) + rowbB + bswz[kk]);
                    const int j = sb * 8 + ntp * 2;
                    mma_f16(sfr[j],     qf[kk], bf[0], bf[1], sfr[j]);
                    mma_f16(sfr[j + 1], qf[kk], bf[2], bf[3], sfr[j + 1]);
                }
            }
        }

        const int r0 = wrow0 + gid;
        const int r1 = r0 + 8;
        if (k0t + 127 > wrow0) {
#pragma unroll
            for (int j = 0; j < 16; j++) {
                int c = k0t + j * 8 + 2 * tig;
                if (c > r0) sfr[j][0] = MASKED_BIAS;
                if (c + 1 > r0) sfr[j][1] = MASKED_BIAS;
                if (c > r1) sfr[j][2] = MASKED_BIAS;
                if (c + 1 > r1) sfr[j][3] = MASKED_BIAS;
            }
        }

        // ---- single online-softmax update per 128 keys ----
        float mx0 = -1e30f, mx1 = -1e30f;
#pragma unroll
        for (int j = 0; j < 16; j++) {
            mx0 = fmaxf(mx0, fmaxf(sfr[j][0], sfr[j][1]));
            mx1 = fmaxf(mx1, fmaxf(sfr[j][2], sfr[j][3]));
        }
        mx0 = fmaxf(mx0, __shfl_xor_sync(0xffffffffu, mx0, 1));
        mx0 = fmaxf(mx0, __shfl_xor_sync(0xffffffffu, mx0, 2));
        mx1 = fmaxf(mx1, __shfl_xor_sync(0xffffffffu, mx1, 1));
        mx1 = fmaxf(mx1, __shfl_xor_sync(0xffffffffu, mx1, 2));

        const float mn0 = fmaxf(m0, mx0);
        const float mn1 = fmaxf(m1, mx1);
        float a0, a1;
        {
            uint32_t sc = ex2h2(packh2((m0 - mn0) * L2E, (m1 - mn1) * L2E));
            float2 scf = __half22float2(*(__half2*)&sc);
            a0 = scf.x; a1 = scf.y;
        }
        m0 = mn0; m1 = mn1;
        const float b0l = m0 * L2E;
        const float b1l = m1 * L2E;

        uint32_t pf[8][4];
#pragma unroll
        for (int j = 0; j < 16; j++) {
            uint32_t ha = packh2(fmaf(sfr[j][0], L2E, -b0l),
                                 fmaf(sfr[j][1], L2E, -b0l));
            uint32_t hb = packh2(fmaf(sfr[j][2], L2E, -b1l),
                                 fmaf(sfr[j][3], L2E, -b1l));
            pf[j >> 1][(j & 1) * 2]     = ex2h2(ha);
            pf[j >> 1][(j & 1) * 2 + 1] = ex2h2(hb);
        }

        float ls0 = 0.f, ls1 = 0.f;
#pragma unroll
        for (int kv = 0; kv < 8; kv++) {
            __half2 s0 = __hadd2(*(__half2*)&pf[kv][0], *(__half2*)&pf[kv][2]);
            __half2 s1 = __hadd2(*(__half2*)&pf[kv][1], *(__half2*)&pf[kv][3]);
            float2 f0 = __half22float2(s0);
            float2 f1 = __half22float2(s1);
            ls0 += f0.x + f0.y;
            ls1 += f1.x + f1.y;
        }
        ls0 += __shfl_xor_sync(0xffffffffu, ls0, 1);
        ls0 += __shfl_xor_sync(0xffffffffu, ls0, 2);
        ls1 += __shfl_xor_sync(0xffffffffu, ls1, 1);
        ls1 += __shfl_xor_sync(0xffffffffu, ls1, 2);
        l0 = l0 * a0 + ls0;
        l1 = l1 * a1 + ls1;

#pragma unroll
        for (int nt = 0; nt < 8; nt++) {
            o[nt][0] *= a0; o[nt][1] *= a0;
            o[nt][2] *= a1; o[nt][3] *= a1;
        }

        // ---- O += P @ V over both subtiles ----
#pragma unroll
        for (int g = 0; g < 8; g++) {
            const uint32_t baseV = base + (g >> 2) * 16384 + 8192;
            const int kkv = g & 3;
#pragma unroll
            for (int ntp = 0; ntp < 4; ntp++) {
                uint32_t bf[4];
                ldsm4(bf, baseV + ntp * (16 * 128) + rowbB + bswz[kkv]);
                mma_f16(o[ntp * 2],     pf[g], bf[0], bf[1], o[ntp * 2]);
                mma_f16(o[ntp * 2 + 1], pf[g], bf[2], bf[3], o[ntp * 2 + 1]);
            }
        }
    }

    const float inv0 = 1.f / l0;
    const float inv1 = 1.f / l1;
    const int r0 = wrow0 + gid;
    uint32_t* ob0 = (uint32_t*)(g_att + ((size_t)(b * S_ + r0)) * D_ + h * HD_);
    uint32_t* ob1 = (uint32_t*)(g_att + ((size_t)(b * S_ + r0 + 8)) * D_ + h * HD_);
#pragma unroll
    for (int nt = 0; nt < 8; nt++) {
        ob0[nt * 4 + tig] = packh2(o[nt][0] * inv0, o[nt][1] * inv0);
        ob1[nt * 4 + tig] = packh2(o[nt][2] * inv1, o[nt][3] * inv1);
    }
}

// ---------------------------------------------------------------------------
extern "C" void kernel_launch(void* const* d_in, const int* in_sizes, int n_in,
                              void* d_out, int out_size)
{
    const float* hidden   = (const float*)d_in[0];
    const float* c_attn_w = (const float*)d_in[1];
    const float* c_attn_b = (const float*)d_in[2];
    const float* c_proj_w = (const float*)d_in[3];
    const float* c_proj_b = (const float*)d_in[4];
    float* out = (float*)d_out;

    constexpr int SMEM_G128 = 3 * (128 + 128) * 128;   // 96KB
    constexpr int SMEM_G64  = 3 * (128 + 64) * 128;    // 72KB
    constexpr int SMEM_ATTN = 2 * 32768;               // 64KB

    static bool attr_set = false;
    if (!attr_set) {
        cudaFuncSetAttribute((const void*)mma_gemm<0, 128, 256, 2>,
            cudaFuncAttributeMaxDynamicSharedMemorySize, SMEM_G128);
        cudaFuncSetAttribute((const void*)mma_gemm<1, 64, 128, 3>,
            cudaFuncAttributeMaxDynamicSharedMemorySize, SMEM_G64);
        cudaFuncSetAttribute((const void*)attn_mma,
            cudaFuncAttributeMaxDynamicSharedMemorySize, SMEM_ATTN);
        attr_set = true;
    }

    __half *px, *pwq, *pwp, *patt;
    cudaGetSymbolAddress((void**)&px, g_x);
    cudaGetSymbolAddress((void**)&pwq, g_wqkv_t);
    cudaGetSymbolAddress((void**)&pwp, g_wp_t);
    cudaGetSymbolAddress((void**)&patt, g_att);

    // Fused pre-pass (1 launch)
    prepass<<<NB_CVT + NB_TQ + NB_TP, 256>>>(hidden, c_attn_w, c_proj_w);

    // Phase 1: QKV GEMM + head split (+ q scaling, v transpose)
    {
        dim3 grid(N_QKV / 128, M_ / 128);   // (18, 32)
        mma_gemm<0, 128, 256, 2><<<grid, 256, SMEM_G128>>>(
            px, pwq, c_attn_b, nullptr, D_, N_QKV);
    }
    // Phase 2: causal flash attention, Br=64, Bc=128
    {
        dim3 grid(S_ / 64, H_, B_);         // (32, 12, 2)
        attn_mma<<<grid, 128, SMEM_ATTN>>>();
    }
    // Phase 3: output projection — 128-thr CTAs, occ 3 -> 384 blocks, 1 wave
    {
        dim3 grid(D_ / 64, M_ / 128);       // (12, 32)
        mma_gemm<1, 64, 128, 3><<<grid, 128, SMEM_G64>>>(
            patt, pwp, c_proj_b, out, D_, D_);
    }
}

// round 15
// speedup vs baseline: 1.2747x; 1.0484x over previous
#include <cuda_runtime.h>
#include <cuda_fp16.h>
#include <cstdint>

// GPT2 attention block, fp16 mma.sync (m16n8k16, fp32 accum) + cp.async.
// B=2, S=2048, D=768, H=12, hd=64

#define B_ 2
#define S_ 2048
#define D_ 768
#define H_ 12
#define HD_ 64
#define M_ (B_ * S_)        // 4096
#define N_QKV (3 * D_)      // 2304
#define MASKED_BIAS (-10000.0f)
#define L2E 1.4426950408889634f

// Scratch (no cudaMalloc allowed) — all fp16
__device__ __align__(128) __half g_q[B_ * H_ * S_ * HD_];   // [b,h,s,d], pre-scaled 1/8
__device__ __align__(128) __half g_k[B_ * H_ * S_ * HD_];   // [b,h,s,d]
__device__ __align__(128) __half g_v[B_ * H_ * S_ * HD_];   // [b,h,d,s]  (TRANSPOSED)
__device__ __align__(128) __half g_att[M_ * D_];
__device__ __align__(128) __half g_x[M_ * D_];              // hidden fp16
__device__ __align__(128) __half g_wqkv_t[N_QKV * D_];      // [n][k]
__device__ __align__(128) __half g_wp_t[D_ * D_];           // [n][k]

// ---------------------------------------------------------------------------
__device__ __forceinline__ uint32_t packh2(float lo, float hi) {
    __half2 h = __floats2half2_rn(lo, hi);
    return *(uint32_t*)&h;
}
__device__ __forceinline__ uint32_t ex2h2(uint32_t x) {
    uint32_t y;
    asm("ex2.approx.f16x2 %0, %1;" : "=r"(y) : "r"(x));
    return y;
}
__device__ __forceinline__ void mma_f16(float d[4], const uint32_t a[4],
                                        const uint32_t b0, const uint32_t b1,
                                        const float c[4]) {
    asm volatile(
        "mma.sync.aligned.m16n8k16.row.col.f32.f16.f16.f32 "
        "{%0,%1,%2,%3}, {%4,%5,%6,%7}, {%8,%9}, {%10,%11,%12,%13};\n"
        : "=f"(d[0]), "=f"(d[1]), "=f"(d[2]), "=f"(d[3])
        : "r"(a[0]), "r"(a[1]), "r"(a[2]), "r"(a[3]),
          "r"(b0), "r"(b1),
          "f"(c[0]), "f"(c[1]), "f"(c[2]), "f"(c[3]));
}
__device__ __forceinline__ void ldsm4(uint32_t r[4], uint32_t addr) {
    asm volatile("ldmatrix.sync.aligned.m8n8.x4.shared.b16 {%0,%1,%2,%3}, [%4];"
        : "=r"(r[0]), "=r"(r[1]), "=r"(r[2]), "=r"(r[3]) : "r"(addr));
}
__device__ __forceinline__ void cp16(uint32_t dst, const void* src) {
    asm volatile("cp.async.cg.shared.global [%0], [%1], 16;\n"
                 :: "r"(dst), "l"(src));
}
__device__ __forceinline__ void cp_commit() {
    asm volatile("cp.async.commit_group;\n");
}
template <int N>
__device__ __forceinline__ void cp_wait() {
    asm volatile("cp.async.wait_group %0;\n" :: "n"(N));
}

// ---------------------------------------------------------------------------
// Fused pre-pass: one launch does hidden cvt + both weight transposes.
// ---------------------------------------------------------------------------
#define NB_CVT (M_ * D_ / 4 / 256)          // 3072
#define NB_TQ  ((N_QKV / 32) * (D_ / 32))   // 1728
#define NB_TP  ((D_ / 32) * (D_ / 32))      // 576

__global__ __launch_bounds__(256) void prepass(
    const float* __restrict__ hidden,
    const float* __restrict__ wq,
    const float* __restrict__ wp)
{
    const int bid = blockIdx.x;
    const int tid = threadIdx.x;

    if (bid < NB_CVT) {
        int i = bid * 256 + tid;
        float4 v = ((const float4*)hidden)[i];
        uint2 t;
        t.x = packh2(v.x, v.y);
        t.y = packh2(v.z, v.w);
        ((uint2*)g_x)[i] = t;
        return;
    }

    const float* src;
    __half* dst;
    int R, C, bx, by;
    if (bid < NB_CVT + NB_TQ) {
        int bi = bid - NB_CVT;
        src = wq; dst = g_wqkv_t; R = D_; C = N_QKV;
        bx = bi % (N_QKV / 32); by = bi / (N_QKV / 32);
    } else {
        int bi = bid - NB_CVT - NB_TQ;
        src = wp; dst = g_wp_t; R = D_; C = D_;
        bx = bi % (D_ / 32); by = bi / (D_ / 32);
    }

    __shared__ float tile[32][33];
    const int c0 = bx * 32, r0 = by * 32;
    const int x = tid & 31, y = tid >> 5;
#pragma unroll
    for (int j = 0; j < 32; j += 8)
        tile[y + j][x] = src[(size_t)(r0 + y + j) * C + c0 + x];
    __syncthreads();
#pragma unroll
    for (int j = 0; j < 32; j += 8)
        dst[(size_t)(c0 + y + j) * R + r0 + x] = __float2half(tile[x][y + j]);
}

// ---------------------------------------------------------------------------
// FP16 GEMM: 128 x BN_ x 64 tile, THREADS threads, cp.async 3-stage,
// XOR-swizzled smem, ldmatrix. Packed (half2/float2) epilogue stores.
//   GEMM1: MODE 0, BN=128, 256 thr, occ 2.
//   proj : MODE 1, BN= 64, 128 thr, occ 3 (384 blocks = single wave).
// ---------------------------------------------------------------------------
template <int MODE, int BN_, int THREADS, int OCC>
__global__ __launch_bounds__(THREADS, OCC) void mma_gemm(
    const __half* __restrict__ A,   // [M][K]
    const __half* __restrict__ Bt,  // [N][K]
    const float* __restrict__ bias,
    float* __restrict__ Cout,
    int K, int N)
{
    constexpr int BM = 128, BN = BN_, BK = 64;            // BK in halfs (128B)
    constexpr int STAGE_BYTES = (BM + BN) * 128;
    constexpr int NWARPS = THREADS / 32;
    constexpr int WN_CNT = BN / 32;
    constexpr int WM_CNT = NWARPS / WN_CNT;
    constexpr int MT = 128 / (WM_CNT * 16);
    constexpr int ROWS_PASS = THREADS / 8;
    constexpr int APASS = BM / ROWS_PASS;
    constexpr int BPASS = BN / ROWS_PASS;

    extern __shared__ uint32_t smem[];
    const uint32_t sbase = (uint32_t)__cvta_generic_to_shared(smem);

    const int tid = threadIdx.x;
    const int lane = tid & 31;
    const int wid = tid >> 5;
    const int wm = wid % WM_CNT, wn = wid / WM_CNT;
    const int gid = lane >> 2, tig = lane & 3, l7 = lane & 7;
    const int bm = blockIdx.y, bn = blockIdx.x;

    const int row_ = tid >> 3, g_ = tid & 7;
    const __half* asrc = A + (size_t)(bm * BM + row_) * K + g_ * 8;
    const __half* bsrc = Bt + (size_t)(bn * BN + row_) * K + g_ * 8;
    const uint32_t dofs = (uint32_t)(row_ * 128 + ((g_ ^ (row_ & 7)) * 16));

    auto issue = [&](int s, int kt) {
        const uint32_t sb = sbase + (uint32_t)(s * STAGE_BYTES);
        const __half* ap = asrc + kt * BK;
        const __half* bp = bsrc + kt * BK;
        const uint32_t ad = sb + dofs;
        const uint32_t bd = ad + (uint32_t)(BM * 128);
#pragma unroll
        for (int u = 0; u < APASS; u++)
            cp16(ad + u * (ROWS_PASS * 128), ap + (size_t)u * ROWS_PASS * K);
#pragma unroll
        for (int u = 0; u < BPASS; u++)
            cp16(bd + u * (ROWS_PASS * 128), bp + (size_t)u * ROWS_PASS * K);
    };

    const uint32_t arowb =
        (uint32_t)((wm * (MT * 16) + l7 + ((lane >> 3) & 1) * 8) * 128);
    const uint32_t browb =
        (uint32_t)((wn * 32 + l7 + ((lane >> 4) & 1) * 8) * 128)
        + (uint32_t)(BM * 128);
    uint32_t aswz[4], bswz[4];
#pragma unroll
    for (int kk = 0; kk < 4; kk++) {
        aswz[kk] = (uint32_t)((((kk * 2 + (lane >> 4)) ^ l7)) * 16);
        bswz[kk] = (uint32_t)((((kk * 2 + ((lane >> 3) & 1)) ^ l7)) * 16);
    }

    float acc[MT][4][4];
#pragma unroll
    for (int i = 0; i < MT; i++)
#pragma unroll
        for (int j = 0; j < 4; j++)
#pragma unroll
            for (int r = 0; r < 4; r++) acc[i][j][r] = 0.f;

    issue(0, 0); cp_commit();
    issue(1, 1); cp_commit();

    const int ksteps = K / BK;   // 12
    int st = 0;
    for (int kt = 0; kt < ksteps; kt++) {
        cp_wait<1>();
        __syncthreads();
        if (kt + 2 < ksteps) {
            int s2 = st + 2; if (s2 >= 3) s2 -= 3;
            issue(s2, kt + 2);
        }
        cp_commit();

        const uint32_t sb = sbase + (uint32_t)(st * STAGE_BYTES);
#pragma unroll
        for (int kk = 0; kk < 4; kk++) {
            uint32_t bf[2][4];
#pragma unroll
            for (int ntp = 0; ntp < 2; ntp++)
                ldsm4(bf[ntp], sb + browb + ntp * (16 * 128) + bswz[kk]);
            uint32_t af[MT][4];
#pragma unroll
            for (int mt = 0; mt < MT; mt++)
                ldsm4(af[mt], sb + arowb + mt * (16 * 128) + aswz[kk]);
#pragma unroll
            for (int mt = 0; mt < MT; mt++)
#pragma unroll
                for (int ntp = 0; ntp < 2; ntp++) {
                    mma_f16(acc[mt][ntp * 2],     af[mt], bf[ntp][0], bf[ntp][1],
                            acc[mt][ntp * 2]);
                    mma_f16(acc[mt][ntp * 2 + 1], af[mt], bf[ntp][2], bf[ntp][3],
                            acc[mt][ntp * 2 + 1]);
                }
        }
        if (++st == 3) st = 0;
    }

    // ---- epilogue: packed stores (n0 = even, pair (n0, n0+1)) ----
#pragma unroll
    for (int mt = 0; mt < MT; mt++) {
#pragma unroll
        for (int nt = 0; nt < 4; nt++) {
            const int n0 = bn * BN + wn * 32 + nt * 8 + 2 * tig;
            const float bz0 = bias[n0], bz1 = bias[n0 + 1];
            const int m0 = bm * BM + wm * (MT * 16) + mt * 16 + gid;
            const int m1 = m0 + 8;
            const float v00 = acc[mt][nt][0] + bz0;
            const float v01 = acc[mt][nt][1] + bz1;
            const float v10 = acc[mt][nt][2] + bz0;
            const float v11 = acc[mt][nt][3] + bz1;
            if (MODE == 0) {
                const int which = n0 / D_;
                const int d2 = n0 - which * D_;
                const int h = d2 >> 6;
                const int hi = d2 & 63;
                const int b0 = m0 >> 11, s0 = m0 & 2047;
                const int b1 = m1 >> 11, s1 = m1 & 2047;
                if (which == 0) {
                    *(uint32_t*)&g_q[(((size_t)(b0 * H_ + h) * S_) + s0) * HD_ + hi] =
                        packh2(v00 * 0.125f, v01 * 0.125f);
                    *(uint32_t*)&g_q[(((size_t)(b1 * H_ + h) * S_) + s1) * HD_ + hi] =
                        packh2(v10 * 0.125f, v11 * 0.125f);
                } else if (which == 1) {
                    *(uint32_t*)&g_k[(((size_t)(b0 * H_ + h) * S_) + s0) * HD_ + hi] =
                        packh2(v00, v01);
                    *(uint32_t*)&g_k[(((size_t)(b1 * H_ + h) * S_) + s1) * HD_ + hi] =
                        packh2(v10, v11);
                } else {
                    __half* vb0 = &g_v[((size_t)(b0 * H_ + h) * HD_ + hi) * S_];
                    __half* vb1 = &g_v[((size_t)(b1 * H_ + h) * HD_ + hi) * S_];
                    vb0[s0] = __float2half(v00);
                    vb0[S_ + s0] = __float2half(v01);
                    vb1[s1] = __float2half(v10);
                    vb1[S_ + s1] = __float2half(v11);
                }
            } else {
                *(float2*)&Cout[(size_t)m0 * N + n0] = make_float2(v00, v01);
                *(float2*)&Cout[(size_t)m1 * N + n0] = make_float2(v10, v11);
            }
        }
    }
}

// ---------------------------------------------------------------------------
// Flash attention, fp16 mma m16n8k16. 128 threads (4 warps), Br=64, Bc=128.
// Block p handles qtile (31-p) then qtile p (balanced pairs: 17 units each).
// 2-stage cp.async double buffer (32KB/stage). occ 3 -> 384 blocks, 1 wave.
// ---------------------------------------------------------------------------
__global__ __launch_bounds__(128, 3) void attn_mma()
{
    const int ppair = blockIdx.x;   // 0..15
    const int h = blockIdx.y;
    const int b = blockIdx.z;
    const int tid = threadIdx.x;
    const int lane = tid & 31;
    const int wid = tid >> 5;
    const int gid = lane >> 2, tig = lane & 3, l7 = lane & 7;
    const int NQT = S_ / 64;        // 32 q-tiles

    const __half* kb = g_k + ((size_t)(b * H_ + h) * S_) * HD_;
    const __half* vtb = g_v + ((size_t)(b * H_ + h) * HD_) * S_;
    const uint32_t* qu = (const uint32_t*)(g_q + ((size_t)(b * H_ + h) * S_) * HD_);

    extern __shared__ uint32_t asmem[];
    const uint32_t sbase = (uint32_t)__cvta_generic_to_shared(asmem);

    const int row_ = tid >> 3, g_ = tid & 7;
    const uint32_t dofs = (uint32_t)(row_ * 128 + ((g_ ^ (row_ & 7)) * 16));

    const uint32_t rowbB = (uint32_t)((l7 + ((lane >> 4) & 1) * 8) * 128);
    uint32_t bswz[4];
#pragma unroll
    for (int kk = 0; kk < 4; kk++)
        bswz[kk] = (uint32_t)((((kk * 2 + ((lane >> 3) & 1)) ^ l7)) * 16);

    auto issueT = [&](int s, int t) {
#pragma unroll
        for (int sb = 0; sb < 2; sb++) {
            const int k0 = t * 128 + sb * 64;
            const uint32_t kd = sbase + (uint32_t)(s * 32768 + sb * 16384) + dofs;
            const uint32_t vd = kd + 8192;
            const __half* kp = kb + (size_t)(k0 + row_) * HD_ + g_ * 8;
            const __half* vp = vtb + (size_t)row_ * S_ + k0 + g_ * 8;
#pragma unroll
            for (int u = 0; u < 4; u++) {
                cp16(kd + u * (16 * 128), kp + (size_t)u * 16 * HD_);
                cp16(vd + u * (16 * 128), vp + (size_t)u * 16 * S_);
            }
        }
    };

    for (int pass = 0; pass < 2; pass++) {
        const int qtile = pass == 0 ? (NQT - 1 - ppair) : ppair;
        const int q0 = qtile * 64;
        const int wrow0 = q0 + wid * 16;
        const int ntiles = qtile / 2 + 1;

        uint32_t qf[4][4];
#pragma unroll
        for (int kk = 0; kk < 4; kk++) {
            const int r0 = wrow0 + gid;
            const int u0 = r0 * 32 + kk * 8 + tig;
            const int u1 = (r0 + 8) * 32 + kk * 8 + tig;
            qf[kk][0] = qu[u0];
            qf[kk][1] = qu[u1];
            qf[kk][2] = qu[u0 + 4];
            qf[kk][3] = qu[u1 + 4];
        }

        float o[8][4];
#pragma unroll
        for (int nt = 0; nt < 8; nt++)
#pragma unroll
            for (int r = 0; r < 4; r++) o[nt][r] = 0.f;
        float m0 = -1e30f, m1 = -1e30f, l0 = 0.f, l1 = 0.f;

        issueT(0, 0); cp_commit();

        for (int t = 0; t < ntiles; t++) {
            cp_wait<0>();
            __syncthreads();
            if (t + 1 < ntiles) {
                issueT((t + 1) & 1, t + 1);
                cp_commit();
            }

            const uint32_t base = sbase + (uint32_t)((t & 1) * 32768);
            const int k0t = t * 128;

            // ---- S = Q @ K^T over 128 keys ----
            float sfr[16][4];
#pragma unroll
            for (int j = 0; j < 16; j++)
#pragma unroll
                for (int r = 0; r < 4; r++) sfr[j][r] = 0.f;
#pragma unroll
            for (int sb = 0; sb < 2; sb++) {
                const uint32_t baseK = base + sb * 16384;
#pragma unroll
                for (int kk = 0; kk < 4; kk++) {
#pragma unroll
                    for (int ntp = 0; ntp < 4; ntp++) {
                        uint32_t bf[4];
                        ldsm4(bf, baseK + ntp * (16 * 128) + rowbB + bswz[kk]);
                        const int j = sb * 8 + ntp * 2;
                        mma_f16(sfr[j],     qf[kk], bf[0], bf[1], sfr[j]);
                        mma_f16(sfr[j + 1], qf[kk], bf[2], bf[3], sfr[j + 1]);
                    }
                }
            }

            const int r0 = wrow0 + gid;
            const int r1 = r0 + 8;
            if (k0t + 127 > wrow0) {
#pragma unroll
                for (int j = 0; j < 16; j++) {
                    int c = k0t + j * 8 + 2 * tig;
                    if (c > r0) sfr[j][0] = MASKED_BIAS;
                    if (c + 1 > r0) sfr[j][1] = MASKED_BIAS;
                    if (c > r1) sfr[j][2] = MASKED_BIAS;
                    if (c + 1 > r1) sfr[j][3] = MASKED_BIAS;
                }
            }

            // ---- single online-softmax update per 128 keys ----
            float mx0 = -1e30f, mx1 = -1e30f;
#pragma unroll
            for (int j = 0; j < 16; j++) {
                mx0 = fmaxf(mx0, fmaxf(sfr[j][0], sfr[j][1]));
                mx1 = fmaxf(mx1, fmaxf(sfr[j][2], sfr[j][3]));
            }
            mx0 = fmaxf(mx0, __shfl_xor_sync(0xffffffffu, mx0, 1));
            mx0 = fmaxf(mx0, __shfl_xor_sync(0xffffffffu, mx0, 2));
            mx1 = fmaxf(mx1, __shfl_xor_sync(0xffffffffu, mx1, 1));
            mx1 = fmaxf(mx1, __shfl_xor_sync(0xffffffffu, mx1, 2));

            const float mn0 = fmaxf(m0, mx0);
            const float mn1 = fmaxf(m1, mx1);
            float a0, a1;
            {
                uint32_t sc = ex2h2(packh2((m0 - mn0) * L2E, (m1 - mn1) * L2E));
                float2 scf = __half22float2(*(__half2*)&sc);
                a0 = scf.x; a1 = scf.y;
            }
            m0 = mn0; m1 = mn1;
            const float b0l = m0 * L2E;
            const float b1l = m1 * L2E;

            uint32_t pf[8][4];
#pragma unroll
            for (int j = 0; j < 16; j++) {
                uint32_t ha = packh2(fmaf(sfr[j][0], L2E, -b0l),
                                     fmaf(sfr[j][1], L2E, -b0l));
                uint32_t hb = packh2(fmaf(sfr[j][2], L2E, -b1l),
                                     fmaf(sfr[j][3], L2E, -b1l));
                pf[j >> 1][(j & 1) * 2]     = ex2h2(ha);
                pf[j >> 1][(j & 1) * 2 + 1] = ex2h2(hb);
            }

            float ls0 = 0.f, ls1 = 0.f;
#pragma unroll
            for (int kv = 0; kv < 8; kv++) {
                __half2 s0 = __hadd2(*(__half2*)&pf[kv][0], *(__half2*)&pf[kv][2]);
                __half2 s1 = __hadd2(*(__half2*)&pf[kv][1], *(__half2*)&pf[kv][3]);
                float2 f0 = __half22float2(s0);
                float2 f1 = __half22float2(s1);
                ls0 += f0.x + f0.y;
                ls1 += f1.x + f1.y;
            }
            ls0 += __shfl_xor_sync(0xffffffffu, ls0, 1);
            ls0 += __shfl_xor_sync(0xffffffffu, ls0, 2);
            ls1 += __shfl_xor_sync(0xffffffffu, ls1, 1);
            ls1 += __shfl_xor_sync(0xffffffffu, ls1, 2);
            l0 = l0 * a0 + ls0;
            l1 = l1 * a1 + ls1;

#pragma unroll
            for (int nt = 0; nt < 8; nt++) {
                o[nt][0] *= a0; o[nt][1] *= a0;
                o[nt][2] *= a1; o[nt][3] *= a1;
            }

            // ---- O += P @ V over both subtiles ----
#pragma unroll
            for (int g = 0; g < 8; g++) {
                const uint32_t baseV = base + (g >> 2) * 16384 + 8192;
                const int kkv = g & 3;
#pragma unroll
                for (int ntp = 0; ntp < 4; ntp++) {
                    uint32_t bf[4];
                    ldsm4(bf, baseV + ntp * (16 * 128) + rowbB + bswz[kkv]);
                    mma_f16(o[ntp * 2],     pf[g], bf[0], bf[1], o[ntp * 2]);
                    mma_f16(o[ntp * 2 + 1], pf[g], bf[2], bf[3], o[ntp * 2 + 1]);
                }
            }
        }

        // epilogue for this pass
        const float inv0 = 1.f / l0;
        const float inv1 = 1.f / l1;
        const int r0 = wrow0 + gid;
        uint32_t* ob0 = (uint32_t*)(g_att + ((size_t)(b * S_ + r0)) * D_ + h * HD_);
        uint32_t* ob1 = (uint32_t*)(g_att + ((size_t)(b * S_ + r0 + 8)) * D_ + h * HD_);
#pragma unroll
        for (int nt = 0; nt < 8; nt++) {
            ob0[nt * 4 + tig] = packh2(o[nt][0] * inv0, o[nt][1] * inv0);
            ob1[nt * 4 + tig] = packh2(o[nt][2] * inv1, o[nt][3] * inv1);
        }

        __syncthreads();   // protect smem ring before next pass
    }
}

// ---------------------------------------------------------------------------
extern "C" void kernel_launch(void* const* d_in, const int* in_sizes, int n_in,
                              void* d_out, int out_size)
{
    const float* hidden   = (const float*)d_in[0];
    const float* c_attn_w = (const float*)d_in[1];
    const float* c_attn_b = (const float*)d_in[2];
    const float* c_proj_w = (const float*)d_in[3];
    const float* c_proj_b = (const float*)d_in[4];
    float* out = (float*)d_out;

    constexpr int SMEM_G128 = 3 * (128 + 128) * 128;   // 96KB
    constexpr int SMEM_G64  = 3 * (128 + 64) * 128;    // 72KB
    constexpr int SMEM_ATTN = 2 * 32768;               // 64KB

    static bool attr_set = false;
    if (!attr_set) {
        cudaFuncSetAttribute((const void*)mma_gemm<0, 128, 256, 2>,
            cudaFuncAttributeMaxDynamicSharedMemorySize, SMEM_G128);
        cudaFuncSetAttribute((const void*)mma_gemm<1, 64, 128, 3>,
            cudaFuncAttributeMaxDynamicSharedMemorySize, SMEM_G64);
        cudaFuncSetAttribute((const void*)attn_mma,
            cudaFuncAttributeMaxDynamicSharedMemorySize, SMEM_ATTN);
        attr_set = true;
    }

    __half *px, *pwq, *pwp, *patt;
    cudaGetSymbolAddress((void**)&px, g_x);
    cudaGetSymbolAddress((void**)&pwq, g_wqkv_t);
    cudaGetSymbolAddress((void**)&pwp, g_wp_t);
    cudaGetSymbolAddress((void**)&patt, g_att);

    // Fused pre-pass (1 launch)
    prepass<<<NB_CVT + NB_TQ + NB_TP, 256>>>(hidden, c_attn_w, c_proj_w);

    // Phase 1: QKV GEMM + head split (+ q scaling, v transpose)
    {
        dim3 grid(N_QKV / 128, M_ / 128);   // (18, 32)
        mma_gemm<0, 128, 256, 2><<<grid, 256, SMEM_G128>>>(
            px, pwq, c_attn_b, nullptr, D_, N_QKV);
    }
    // Phase 2: causal flash attention — paired q-tiles, 384 balanced blocks
    {
        dim3 grid(S_ / 128, H_, B_);        // (16, 12, 2)
        attn_mma<<<grid, 128, SMEM_ATTN>>>();
    }
    // Phase 3: output projection — 128-thr CTAs, occ 3 -> 384 blocks, 1 wave
    {
        dim3 grid(D_ / 64, M_ / 128);       // (12, 32)
        mma_gemm<1, 64, 128, 3><<<grid, 128, SMEM_G64>>>(
            patt, pwp, c_proj_b, out, D_, D_);
    }
}

// round 16
// speedup vs baseline: 1.2952x; 1.0161x over previous
#include <cuda_runtime.h>
#include <cuda_fp16.h>
#include <cstdint>

// GPT2 attention block, fp16 mma.sync (m16n8k16, fp32 accum) + cp.async.
// B=2, S=2048, D=768, H=12, hd=64

#define B_ 2
#define S_ 2048
#define D_ 768
#define H_ 12
#define HD_ 64
#define M_ (B_ * S_)        // 4096
#define N_QKV (3 * D_)      // 2304
#define MASKED_BIAS (-10000.0f)
#define L2E 1.4426950408889634f

// Scratch (no cudaMalloc allowed) — all fp16
__device__ __align__(128) __half g_q[B_ * H_ * S_ * HD_];   // [b,h,s,d], pre-scaled 1/8
__device__ __align__(128) __half g_k[B_ * H_ * S_ * HD_];   // [b,h,s,d]
__device__ __align__(128) __half g_v[B_ * H_ * S_ * HD_];   // [b,h,d,s]  (TRANSPOSED)
__device__ __align__(128) __half g_att[M_ * D_];
__device__ __align__(128) __half g_x[M_ * D_];              // hidden fp16
__device__ __align__(128) __half g_wqkv_t[N_QKV * D_];      // [n][k]
__device__ __align__(128) __half g_wp_t[D_ * D_];           // [n][k]

// ---------------------------------------------------------------------------
__device__ __forceinline__ uint32_t packh2(float lo, float hi) {
    __half2 h = __floats2half2_rn(lo, hi);
    return *(uint32_t*)&h;
}
__device__ __forceinline__ uint32_t ex2h2(uint32_t x) {
    uint32_t y;
    asm("ex2.approx.f16x2 %0, %1;" : "=r"(y) : "r"(x));
    return y;
}
__device__ __forceinline__ void mma_f16(float d[4], const uint32_t a[4],
                                        const uint32_t b0, const uint32_t b1,
                                        const float c[4]) {
    asm volatile(
        "mma.sync.aligned.m16n8k16.row.col.f32.f16.f16.f32 "
        "{%0,%1,%2,%3}, {%4,%5,%6,%7}, {%8,%9}, {%10,%11,%12,%13};\n"
        : "=f"(d[0]), "=f"(d[1]), "=f"(d[2]), "=f"(d[3])
        : "r"(a[0]), "r"(a[1]), "r"(a[2]), "r"(a[3]),
          "r"(b0), "r"(b1),
          "f"(c[0]), "f"(c[1]), "f"(c[2]), "f"(c[3]));
}
__device__ __forceinline__ void ldsm4(uint32_t r[4], uint32_t addr) {
    asm volatile("ldmatrix.sync.aligned.m8n8.x4.shared.b16 {%0,%1,%2,%3}, [%4];"
        : "=r"(r[0]), "=r"(r[1]), "=r"(r[2]), "=r"(r[3]) : "r"(addr));
}
__device__ __forceinline__ void cp16(uint32_t dst, const void* src) {
    asm volatile("cp.async.cg.shared.global [%0], [%1], 16;\n"
                 :: "r"(dst), "l"(src));
}
__device__ __forceinline__ void cp_commit() {
    asm volatile("cp.async.commit_group;\n");
}
template <int N>
__device__ __forceinline__ void cp_wait() {
    asm volatile("cp.async.wait_group %0;\n" :: "n"(N));
}

// ---------------------------------------------------------------------------
// Fused pre-pass: one launch does hidden cvt + both weight transposes.
// ---------------------------------------------------------------------------
#define NB_CVT (M_ * D_ / 4 / 256)          // 3072
#define NB_TQ  ((N_QKV / 32) * (D_ / 32))   // 1728
#define NB_TP  ((D_ / 32) * (D_ / 32))      // 576

__global__ __launch_bounds__(256) void prepass(
    const float* __restrict__ hidden,
    const float* __restrict__ wq,
    const float* __restrict__ wp)
{
    const int bid = blockIdx.x;
    const int tid = threadIdx.x;

    if (bid < NB_CVT) {
        int i = bid * 256 + tid;
        float4 v = ((const float4*)hidden)[i];
        uint2 t;
        t.x = packh2(v.x, v.y);
        t.y = packh2(v.z, v.w);
        ((uint2*)g_x)[i] = t;
        return;
    }

    const float* src;
    __half* dst;
    int R, C, bx, by;
    if (bid < NB_CVT + NB_TQ) {
        int bi = bid - NB_CVT;
        src = wq; dst = g_wqkv_t; R = D_; C = N_QKV;
        bx = bi % (N_QKV / 32); by = bi / (N_QKV / 32);
    } else {
        int bi = bid - NB_CVT - NB_TQ;
        src = wp; dst = g_wp_t; R = D_; C = D_;
        bx = bi % (D_ / 32); by = bi / (D_ / 32);
    }

    __shared__ float tile[32][33];
    const int c0 = bx * 32, r0 = by * 32;
    const int x = tid & 31, y = tid >> 5;
#pragma unroll
    for (int j = 0; j < 32; j += 8)
        tile[y + j][x] = src[(size_t)(r0 + y + j) * C + c0 + x];
    __syncthreads();
#pragma unroll
    for (int j = 0; j < 32; j += 8)
        dst[(size_t)(c0 + y + j) * R + r0 + x] = __float2half(tile[x][y + j]);
}

// ---------------------------------------------------------------------------
// FP16 GEMM: 128 x BN_ x 64 tile, THREADS threads, cp.async 3-stage,
// XOR-swizzled smem, ldmatrix. Packed (half2/float2) epilogue stores.
//   GEMM1: MODE 0, BN=128, 256 thr, occ 2.
//   proj : MODE 1, BN= 64, 128 thr, occ 3 (384 blocks = single wave).
// ---------------------------------------------------------------------------
template <int MODE, int BN_, int THREADS, int OCC>
__global__ __launch_bounds__(THREADS, OCC) void mma_gemm(
    const __half* __restrict__ A,   // [M][K]
    const __half* __restrict__ Bt,  // [N][K]
    const float* __restrict__ bias,
    float* __restrict__ Cout,
    int K, int N)
{
    constexpr int BM = 128, BN = BN_, BK = 64;            // BK in halfs (128B)
    constexpr int STAGE_BYTES = (BM + BN) * 128;
    constexpr int NWARPS = THREADS / 32;
    constexpr int WN_CNT = BN / 32;
    constexpr int WM_CNT = NWARPS / WN_CNT;
    constexpr int MT = 128 / (WM_CNT * 16);
    constexpr int ROWS_PASS = THREADS / 8;
    constexpr int APASS = BM / ROWS_PASS;
    constexpr int BPASS = BN / ROWS_PASS;

    extern __shared__ uint32_t smem[];
    const uint32_t sbase = (uint32_t)__cvta_generic_to_shared(smem);

    const int tid = threadIdx.x;
    const int lane = tid & 31;
    const int wid = tid >> 5;
    const int wm = wid % WM_CNT, wn = wid / WM_CNT;
    const int gid = lane >> 2, tig = lane & 3, l7 = lane & 7;
    const int bm = blockIdx.y, bn = blockIdx.x;

    const int row_ = tid >> 3, g_ = tid & 7;
    const __half* asrc = A + (size_t)(bm * BM + row_) * K + g_ * 8;
    const __half* bsrc = Bt + (size_t)(bn * BN + row_) * K + g_ * 8;
    const uint32_t dofs = (uint32_t)(row_ * 128 + ((g_ ^ (row_ & 7)) * 16));

    auto issue = [&](int s, int kt) {
        const uint32_t sb = sbase + (uint32_t)(s * STAGE_BYTES);
        const __half* ap = asrc + kt * BK;
        const __half* bp = bsrc + kt * BK;
        const uint32_t ad = sb + dofs;
        const uint32_t bd = ad + (uint32_t)(BM * 128);
#pragma unroll
        for (int u = 0; u < APASS; u++)
            cp16(ad + u * (ROWS_PASS * 128), ap + (size_t)u * ROWS_PASS * K);
#pragma unroll
        for (int u = 0; u < BPASS; u++)
            cp16(bd + u * (ROWS_PASS * 128), bp + (size_t)u * ROWS_PASS * K);
    };

    const uint32_t arowb =
        (uint32_t)((wm * (MT * 16) + l7 + ((lane >> 3) & 1) * 8) * 128);
    const uint32_t browb =
        (uint32_t)((wn * 32 + l7 + ((lane >> 4) & 1) * 8) * 128)
        + (uint32_t)(BM * 128);
    uint32_t aswz[4], bswz[4];
#pragma unroll
    for (int kk = 0; kk < 4; kk++) {
        aswz[kk] = (uint32_t)((((kk * 2 + (lane >> 4)) ^ l7)) * 16);
        bswz[kk] = (uint32_t)((((kk * 2 + ((lane >> 3) & 1)) ^ l7)) * 16);
    }

    float acc[MT][4][4];
#pragma unroll
    for (int i = 0; i < MT; i++)
#pragma unroll
        for (int j = 0; j < 4; j++)
#pragma unroll
            for (int r = 0; r < 4; r++) acc[i][j][r] = 0.f;

    issue(0, 0); cp_commit();
    issue(1, 1); cp_commit();

    const int ksteps = K / BK;   // 12
    int st = 0;
    for (int kt = 0; kt < ksteps; kt++) {
        cp_wait<1>();
        __syncthreads();
        if (kt + 2 < ksteps) {
            int s2 = st + 2; if (s2 >= 3) s2 -= 3;
            issue(s2, kt + 2);
        }
        cp_commit();

        const uint32_t sb = sbase + (uint32_t)(st * STAGE_BYTES);
#pragma unroll
        for (int kk = 0; kk < 4; kk++) {
            uint32_t bf[2][4];
#pragma unroll
            for (int ntp = 0; ntp < 2; ntp++)
                ldsm4(bf[ntp], sb + browb + ntp * (16 * 128) + bswz[kk]);
            uint32_t af[MT][4];
#pragma unroll
            for (int mt = 0; mt < MT; mt++)
                ldsm4(af[mt], sb + arowb + mt * (16 * 128) + aswz[kk]);
#pragma unroll
            for (int mt = 0; mt < MT; mt++)
#pragma unroll
                for (int ntp = 0; ntp < 2; ntp++) {
                    mma_f16(acc[mt][ntp * 2],     af[mt], bf[ntp][0], bf[ntp][1],
                            acc[mt][ntp * 2]);
                    mma_f16(acc[mt][ntp * 2 + 1], af[mt], bf[ntp][2], bf[ntp][3],
                            acc[mt][ntp * 2 + 1]);
                }
        }
        if (++st == 3) st = 0;
    }

    // ---- epilogue: packed stores (n0 = even, pair (n0, n0+1)) ----
#pragma unroll
    for (int mt = 0; mt < MT; mt++) {
#pragma unroll
        for (int nt = 0; nt < 4; nt++) {
            const int n0 = bn * BN + wn * 32 + nt * 8 + 2 * tig;
            const float bz0 = bias[n0], bz1 = bias[n0 + 1];
            const int m0 = bm * BM + wm * (MT * 16) + mt * 16 + gid;
            const int m1 = m0 + 8;
            const float v00 = acc[mt][nt][0] + bz0;
            const float v01 = acc[mt][nt][1] + bz1;
            const float v10 = acc[mt][nt][2] + bz0;
            const float v11 = acc[mt][nt][3] + bz1;
            if (MODE == 0) {
                const int which = n0 / D_;
                const int d2 = n0 - which * D_;
                const int h = d2 >> 6;
                const int hi = d2 & 63;
                const int b0 = m0 >> 11, s0 = m0 & 2047;
                const int b1 = m1 >> 11, s1 = m1 & 2047;
                if (which == 0) {
                    *(uint32_t*)&g_q[(((size_t)(b0 * H_ + h) * S_) + s0) * HD_ + hi] =
                        packh2(v00 * 0.125f, v01 * 0.125f);
                    *(uint32_t*)&g_q[(((size_t)(b1 * H_ + h) * S_) + s1) * HD_ + hi] =
                        packh2(v10 * 0.125f, v11 * 0.125f);
                } else if (which == 1) {
                    *(uint32_t*)&g_k[(((size_t)(b0 * H_ + h) * S_) + s0) * HD_ + hi] =
                        packh2(v00, v01);
                    *(uint32_t*)&g_k[(((size_t)(b1 * H_ + h) * S_) + s1) * HD_ + hi] =
                        packh2(v10, v11);
                } else {
                    __half* vb0 = &g_v[((size_t)(b0 * H_ + h) * HD_ + hi) * S_];
                    __half* vb1 = &g_v[((size_t)(b1 * H_ + h) * HD_ + hi) * S_];
                    vb0[s0] = __float2half(v00);
                    vb0[S_ + s0] = __float2half(v01);
                    vb1[s1] = __float2half(v10);
                    vb1[S_ + s1] = __float2half(v11);
                }
            } else {
                *(float2*)&Cout[(size_t)m0 * N + n0] = make_float2(v00, v01);
                *(float2*)&Cout[(size_t)m1 * N + n0] = make_float2(v10, v11);
            }
        }
    }
}

// ---------------------------------------------------------------------------
// Flash attention, fp16 mma m16n8k16. 128 threads (4 warps), Br=64.
// Block p handles qtile (31-p) then qtile p. Per pass: ⌊(q+1)/2⌋ full
// 128-key tiles + a 64-key causal tail when q is even (no dead subtile).
// 2-stage cp.async double buffer (32KB/stage). occ 3 -> 384 blocks, 1 wave.
// ---------------------------------------------------------------------------
__global__ __launch_bounds__(128, 3) void attn_mma()
{
    const int ppair = blockIdx.x;   // 0..15
    const int h = blockIdx.y;
    const int b = blockIdx.z;
    const int tid = threadIdx.x;
    const int lane = tid & 31;
    const int wid = tid >> 5;
    const int gid = lane >> 2, tig = lane & 3, l7 = lane & 7;
    const int NQT = S_ / 64;        // 32 q-tiles

    const __half* kb = g_k + ((size_t)(b * H_ + h) * S_) * HD_;
    const __half* vtb = g_v + ((size_t)(b * H_ + h) * HD_) * S_;
    const uint32_t* qu = (const uint32_t*)(g_q + ((size_t)(b * H_ + h) * S_) * HD_);

    extern __shared__ uint32_t asmem[];
    const uint32_t sbase = (uint32_t)__cvta_generic_to_shared(asmem);

    const int row_ = tid >> 3, g_ = tid & 7;
    const uint32_t dofs = (uint32_t)(row_ * 128 + ((g_ ^ (row_ & 7)) * 16));

    const uint32_t rowbB = (uint32_t)((l7 + ((lane >> 4) & 1) * 8) * 128);
    uint32_t bswz[4];
#pragma unroll
    for (int kk = 0; kk < 4; kk++)
        bswz[kk] = (uint32_t)((((kk * 2 + ((lane >> 3) & 1)) ^ l7)) * 16);

    // full 128-key tile load (both subtiles)
    auto issueT = [&](int s, int t) {
#pragma unroll
        for (int sb = 0; sb < 2; sb++) {
            const int k0 = t * 128 + sb * 64;
            const uint32_t kd = sbase + (uint32_t)(s * 32768 + sb * 16384) + dofs;
            const uint32_t vd = kd + 8192;
            const __half* kp = kb + (size_t)(k0 + row_) * HD_ + g_ * 8;
            const __half* vp = vtb + (size_t)row_ * S_ + k0 + g_ * 8;
#pragma unroll
            for (int u = 0; u < 4; u++) {
                cp16(kd + u * (16 * 128), kp + (size_t)u * 16 * HD_);
                cp16(vd + u * (16 * 128), vp + (size_t)u * 16 * S_);
            }
        }
    };
    // 64-key tail load (first subtile slot only)
    auto issueTail = [&](int s, int t) {
        const int k0 = t * 128;
        const uint32_t kd = sbase + (uint32_t)(s * 32768) + dofs;
        const uint32_t vd = kd + 8192;
        const __half* kp = kb + (size_t)(k0 + row_) * HD_ + g_ * 8;
        const __half* vp = vtb + (size_t)row_ * S_ + k0 + g_ * 8;
#pragma unroll
        for (int u = 0; u < 4; u++) {
            cp16(kd + u * (16 * 128), kp + (size_t)u * 16 * HD_);
            cp16(vd + u * (16 * 128), vp + (size_t)u * 16 * S_);
        }
    };

    for (int pass = 0; pass < 2; pass++) {
        const int qtile = pass == 0 ? (NQT - 1 - ppair) : ppair;
        const int q0 = qtile * 64;
        const int wrow0 = q0 + wid * 16;
        const int ksubs = qtile + 1;          // 64-key subtiles needed
        const int nfull = ksubs >> 1;         // full 128-key tiles
        const bool has_tail = (ksubs & 1);    // qtile even

        uint32_t qf[4][4];
#pragma unroll
        for (int kk = 0; kk < 4; kk++) {
            const int r0 = wrow0 + gid;
            const int u0 = r0 * 32 + kk * 8 + tig;
            const int u1 = (r0 + 8) * 32 + kk * 8 + tig;
            qf[kk][0] = qu[u0];
            qf[kk][1] = qu[u1];
            qf[kk][2] = qu[u0 + 4];
            qf[kk][3] = qu[u1 + 4];
        }

        float o[8][4];
#pragma unroll
        for (int nt = 0; nt < 8; nt++)
#pragma unroll
            for (int r = 0; r < 4; r++) o[nt][r] = 0.f;
        float m0 = -1e30f, m1 = -1e30f, l0 = 0.f, l1 = 0.f;

        if (nfull > 0) issueT(0, 0); else issueTail(0, 0);
        cp_commit();

        const int r0 = wrow0 + gid;
        const int r1 = r0 + 8;

        for (int t = 0; t < nfull; t++) {
            cp_wait<0>();
            __syncthreads();
            if (t + 1 < nfull) issueT((t + 1) & 1, t + 1);
            else if (has_tail) issueTail((t + 1) & 1, nfull);
            cp_commit();

            const uint32_t base = sbase + (uint32_t)((t & 1) * 32768);
            const int k0t = t * 128;

            float sfr[16][4];
#pragma unroll
            for (int j = 0; j < 16; j++)
#pragma unroll
                for (int r = 0; r < 4; r++) sfr[j][r] = 0.f;
#pragma unroll
            for (int sb = 0; sb < 2; sb++) {
                const uint32_t baseK = base + sb * 16384;
#pragma unroll
                for (int kk = 0; kk < 4; kk++) {
#pragma unroll
                    for (int ntp = 0; ntp < 4; ntp++) {
                        uint32_t bf[4];
                        ldsm4(bf, baseK + ntp * (16 * 128) + rowbB + bswz[kk]);
                        const int j = sb * 8 + ntp * 2;
                        mma_f16(sfr[j],     qf[kk], bf[0], bf[1], sfr[j]);
                        mma_f16(sfr[j + 1], qf[kk], bf[2], bf[3], sfr[j + 1]);
                    }
                }
            }

            if (k0t + 127 > wrow0) {
#pragma unroll
                for (int j = 0; j < 16; j++) {
                    int c = k0t + j * 8 + 2 * tig;
                    if (c > r0) sfr[j][0] = MASKED_BIAS;
                    if (c + 1 > r0) sfr[j][1] = MASKED_BIAS;
                    if (c > r1) sfr[j][2] = MASKED_BIAS;
                    if (c + 1 > r1) sfr[j][3] = MASKED_BIAS;
                }
            }

            float mx0 = -1e30f, mx1 = -1e30f;
#pragma unroll
            for (int j = 0; j < 16; j++) {
                mx0 = fmaxf(mx0, fmaxf(sfr[j][0], sfr[j][1]));
                mx1 = fmaxf(mx1, fmaxf(sfr[j][2], sfr[j][3]));
            }
            mx0 = fmaxf(mx0, __shfl_xor_sync(0xffffffffu, mx0, 1));
            mx0 = fmaxf(mx0, __shfl_xor_sync(0xffffffffu, mx0, 2));
            mx1 = fmaxf(mx1, __shfl_xor_sync(0xffffffffu, mx1, 1));
            mx1 = fmaxf(mx1, __shfl_xor_sync(0xffffffffu, mx1, 2));

            const float mn0 = fmaxf(m0, mx0);
            const float mn1 = fmaxf(m1, mx1);
            float a0, a1;
            {
                uint32_t sc = ex2h2(packh2((m0 - mn0) * L2E, (m1 - mn1) * L2E));
                float2 scf = __half22float2(*(__half2*)&sc);
                a0 = scf.x; a1 = scf.y;
            }
            m0 = mn0; m1 = mn1;
            const float b0l = m0 * L2E;
            const float b1l = m1 * L2E;

            uint32_t pf[8][4];
#pragma unroll
            for (int j = 0; j < 16; j++) {
                uint32_t ha = packh2(fmaf(sfr[j][0], L2E, -b0l),
                                     fmaf(sfr[j][1], L2E, -b0l));
                uint32_t hb = packh2(fmaf(sfr[j][2], L2E, -b1l),
                                     fmaf(sfr[j][3], L2E, -b1l));
                pf[j >> 1][(j & 1) * 2]     = ex2h2(ha);
                pf[j >> 1][(j & 1) * 2 + 1] = ex2h2(hb);
            }

            float ls0 = 0.f, ls1 = 0.f;
#pragma unroll
            for (int kv = 0; kv < 8; kv++) {
                __half2 s0 = __hadd2(*(__half2*)&pf[kv][0], *(__half2*)&pf[kv][2]);
                __half2 s1 = __hadd2(*(__half2*)&pf[kv][1], *(__half2*)&pf[kv][3]);
                float2 f0 = __half22float2(s0);
                float2 f1 = __half22float2(s1);
                ls0 += f0.x + f0.y;
                ls1 += f1.x + f1.y;
            }
            ls0 += __shfl_xor_sync(0xffffffffu, ls0, 1);
            ls0 += __shfl_xor_sync(0xffffffffu, ls0, 2);
            ls1 += __shfl_xor_sync(0xffffffffu, ls1, 1);
            ls1 += __shfl_xor_sync(0xffffffffu, ls1, 2);
            l0 = l0 * a0 + ls0;
            l1 = l1 * a1 + ls1;

#pragma unroll
            for (int nt = 0; nt < 8; nt++) {
                o[nt][0] *= a0; o[nt][1] *= a0;
                o[nt][2] *= a1; o[nt][3] *= a1;
            }

#pragma unroll
            for (int g = 0; g < 8; g++) {
                const uint32_t baseV = base + (g >> 2) * 16384 + 8192;
                const int kkv = g & 3;
#pragma unroll
                for (int ntp = 0; ntp < 4; ntp++) {
                    uint32_t bf[4];
                    ldsm4(bf, baseV + ntp * (16 * 128) + rowbB + bswz[kkv]);
                    mma_f16(o[ntp * 2],     pf[g], bf[0], bf[1], o[ntp * 2]);
                    mma_f16(o[ntp * 2 + 1], pf[g], bf[2], bf[3], o[ntp * 2 + 1]);
                }
            }
        }

        // ---- 64-key causal tail (qtile even): keys [q0, q0+64) ----
        if (has_tail) {
            cp_wait<0>();
            __syncthreads();
            const uint32_t base = sbase + (uint32_t)((nfull & 1) * 32768);
            const int k0t = nfull * 128;   // == q0

            float sfr[8][4];
#pragma unroll
            for (int j = 0; j < 8; j++)
#pragma unroll
                for (int r = 0; r < 4; r++) sfr[j][r] = 0.f;
#pragma unroll
            for (int kk = 0; kk < 4; kk++) {
#pragma unroll
                for (int ntp = 0; ntp < 4; ntp++) {
                    uint32_t bf[4];
                    ldsm4(bf, base + ntp * (16 * 128) + rowbB + bswz[kk]);
                    mma_f16(sfr[ntp * 2],     qf[kk], bf[0], bf[1], sfr[ntp * 2]);
                    mma_f16(sfr[ntp * 2 + 1], qf[kk], bf[2], bf[3], sfr[ntp * 2 + 1]);
                }
            }
#pragma unroll
            for (int j = 0; j < 8; j++) {
                int c = k0t + j * 8 + 2 * tig;
                if (c > r0) sfr[j][0] = MASKED_BIAS;
                if (c + 1 > r0) sfr[j][1] = MASKED_BIAS;
                if (c > r1) sfr[j][2] = MASKED_BIAS;
                if (c + 1 > r1) sfr[j][3] = MASKED_BIAS;
            }

            float mx0 = -1e30f, mx1 = -1e30f;
#pragma unroll
            for (int j = 0; j < 8; j++) {
                mx0 = fmaxf(mx0, fmaxf(sfr[j][0], sfr[j][1]));
                mx1 = fmaxf(mx1, fmaxf(sfr[j][2], sfr[j][3]));
            }
            mx0 = fmaxf(mx0, __shfl_xor_sync(0xffffffffu, mx0, 1));
            mx0 = fmaxf(mx0, __shfl_xor_sync(0xffffffffu, mx0, 2));
            mx1 = fmaxf(mx1, __shfl_xor_sync(0xffffffffu, mx1, 1));
            mx1 = fmaxf(mx1, __shfl_xor_sync(0xffffffffu, mx1, 2));

            const float mn0 = fmaxf(m0, mx0);
            const float mn1 = fmaxf(m1, mx1);
            float a0, a1;
            {
                uint32_t sc = ex2h2(packh2((m0 - mn0) * L2E, (m1 - mn1) * L2E));
                float2 scf = __half22float2(*(__half2*)&sc);
                a0 = scf.x; a1 = scf.y;
            }
            m0 = mn0; m1 = mn1;
            const float b0l = m0 * L2E;
            const float b1l = m1 * L2E;

            uint32_t pf[4][4];
#pragma unroll
            for (int j = 0; j < 8; j++) {
                uint32_t ha = packh2(fmaf(sfr[j][0], L2E, -b0l),
                                     fmaf(sfr[j][1], L2E, -b0l));
                uint32_t hb = packh2(fmaf(sfr[j][2], L2E, -b1l),
                                     fmaf(sfr[j][3], L2E, -b1l));
                pf[j >> 1][(j & 1) * 2]     = ex2h2(ha);
                pf[j >> 1][(j & 1) * 2 + 1] = ex2h2(hb);
            }

            float ls0 = 0.f, ls1 = 0.f;
#pragma unroll
            for (int kv = 0; kv < 4; kv++) {
                __half2 s0 = __hadd2(*(__half2*)&pf[kv][0], *(__half2*)&pf[kv][2]);
                __half2 s1 = __hadd2(*(__half2*)&pf[kv][1], *(__half2*)&pf[kv][3]);
                float2 f0 = __half22float2(s0);
                float2 f1 = __half22float2(s1);
                ls0 += f0.x + f0.y;
                ls1 += f1.x + f1.y;
            }
            ls0 += __shfl_xor_sync(0xffffffffu, ls0, 1);
            ls0 += __shfl_xor_sync(0xffffffffu, ls0, 2);
            ls1 += __shfl_xor_sync(0xffffffffu, ls1, 1);
            ls1 += __shfl_xor_sync(0xffffffffu, ls1, 2);
            l0 = l0 * a0 + ls0;
            l1 = l1 * a1 + ls1;

#pragma unroll
            for (int nt = 0; nt < 8; nt++) {
                o[nt][0] *= a0; o[nt][1] *= a0;
                o[nt][2] *= a1; o[nt][3] *= a1;
            }

            const uint32_t baseV = base + 8192;
#pragma unroll
            for (int kkv = 0; kkv < 4; kkv++) {
#pragma unroll
                for (int ntp = 0; ntp < 4; ntp++) {
                    uint32_t bf[4];
                    ldsm4(bf, baseV + ntp * (16 * 128) + rowbB + bswz[kkv]);
                    mma_f16(o[ntp * 2],     pf[kkv], bf[0], bf[1], o[ntp * 2]);
                    mma_f16(o[ntp * 2 + 1], pf[kkv], bf[2], bf[3], o[ntp * 2 + 1]);
                }
            }
        }

        // ---- epilogue for this pass ----
        const float inv0 = 1.f / l0;
        const float inv1 = 1.f / l1;
        uint32_t* ob0 = (uint32_t*)(g_att + ((size_t)(b * S_ + r0)) * D_ + h * HD_);
        uint32_t* ob1 = (uint32_t*)(g_att + ((size_t)(b * S_ + r0 + 8)) * D_ + h * HD_);
#pragma unroll
        for (int nt = 0; nt < 8; nt++) {
            ob0[nt * 4 + tig] = packh2(o[nt][0] * inv0, o[nt][1] * inv0);
            ob1[nt * 4 + tig] = packh2(o[nt][2] * inv1, o[nt][3] * inv1);
        }

        __syncthreads();   // protect smem ring before next pass
    }
}

// ---------------------------------------------------------------------------
extern "C" void kernel_launch(void* const* d_in, const int* in_sizes, int n_in,
                              void* d_out, int out_size)
{
    const float* hidden   = (const float*)d_in[0];
    const float* c_attn_w = (const float*)d_in[1];
    const float* c_attn_b = (const float*)d_in[2];
    const float* c_proj_w = (const float*)d_in[3];
    const float* c_proj_b = (const float*)d_in[4];
    float* out = (float*)d_out;

    constexpr int SMEM_G128 = 3 * (128 + 128) * 128;   // 96KB
    constexpr int SMEM_G64  = 3 * (128 + 64) * 128;    // 72KB
    constexpr int SMEM_ATTN = 2 * 32768;               // 64KB

    static bool attr_set = false;
    if (!attr_set) {
        cudaFuncSetAttribute((const void*)mma_gemm<0, 128, 256, 2>,
            cudaFuncAttributeMaxDynamicSharedMemorySize, SMEM_G128);
        cudaFuncSetAttribute((const void*)mma_gemm<1, 64, 128, 3>,
            cudaFuncAttributeMaxDynamicSharedMemorySize, SMEM_G64);
        cudaFuncSetAttribute((const void*)attn_mma,
            cudaFuncAttributeMaxDynamicSharedMemorySize, SMEM_ATTN);
        attr_set = true;
    }

    __half *px, *pwq, *pwp, *patt;
    cudaGetSymbolAddress((void**)&px, g_x);
    cudaGetSymbolAddress((void**)&pwq, g_wqkv_t);
    cudaGetSymbolAddress((void**)&pwp, g_wp_t);
    cudaGetSymbolAddress((void**)&patt, g_att);

    // Fused pre-pass (1 launch)
    prepass<<<NB_CVT + NB_TQ + NB_TP, 256>>>(hidden, c_attn_w, c_proj_w);

    // Phase 1: QKV GEMM + head split (+ q scaling, v transpose)
    {
        dim3 grid(N_QKV / 128, M_ / 128);   // (18, 32)
        mma_gemm<0, 128, 256, 2><<<grid, 256, SMEM_G128>>>(
            px, pwq, c_attn_b, nullptr, D_, N_QKV);
    }
    // Phase 2: causal flash attention — paired q-tiles, exact subtile count
    {
        dim3 grid(S_ / 128, H_, B_);        // (16, 12, 2)
        attn_mma<<<grid, 128, SMEM_ATTN>>>();
    }
    // Phase 3: output projection — 128-thr CTAs, occ 3 -> 384 blocks, 1 wave
    {
        dim3 grid(D_ / 64, M_ / 128);       // (12, 32)
        mma_gemm<1, 64, 128, 3><<<grid, 128, SMEM_G64>>>(
            patt, pwp, c_proj_b, out, D_, D_);
    }
}